// round 6
// baseline (speedup 1.0000x reference)
#include <cuda_runtime.h>
#include <cuda_bf16.h>
#include <math.h>
#include <stdint.h>

#define Bq   1024
#define Ndim 128
#define Mcb  8192
#define Spay 256
#define EPST 1e-3f
#define PI_F 3.14159265358979323846f
#define TINY 1.17549435e-38f

__constant__ float GHT[8] = {
    -2.9306374202572440f, -1.9816567566958429f, -1.1571937124467802f, -0.3811869902073221f,
     0.3811869902073221f,  1.1571937124467802f,  1.9816567566958429f,  2.9306374202572440f};
__constant__ float GHW[8] = {
    1.9960407221136762e-04f, 1.7077983007413475e-02f, 2.0780232581489188e-01f, 6.6114701255824130e-01f,
    6.6114701255824130e-01f, 2.0780232581489188e-01f, 1.7077983007413475e-02f, 1.9960407221136762e-04f};

// ---------------- scratch ----------------
// int8 2-level quantized operands. A vars: 0=[zr|zi], 1=[ur|ui]. B vars: 0=[ar|ai], 1=[-ai|ar], 2=[br|bi]
__device__ __align__(16) int8_t g_A1[2][Bq * 256];          // X1
__device__ __align__(16) int8_t g_Ax[2][Bq * 512];          // [X1 | X2]
__device__ __align__(16) int8_t g_B1[3][Mcb * 256];         // Y1
__device__ __align__(16) int8_t g_Bx[3][Mcb * 512];         // [Y2 | Y1]
__device__ __align__(16) float  g_sA[2][Bq];                // per-row scales
__device__ __align__(16) float  g_sB[3][Mcb];
// payload + weights (bf16 hi/lo, unchanged)
__device__ __align__(16) __nv_bfloat16 g_Tth[512 * Mcb];
__device__ __align__(16) __nv_bfloat16 g_Ttl[512 * Mcb];
__device__ __align__(16) __nv_bfloat16 g_Whi[(size_t)Bq * Mcb];
__device__ __align__(16) __nv_bfloat16 g_Wlo[(size_t)Bq * Mcb];
// scalars
__device__ __align__(16) float g_cr[Mcb], g_ci[Mcb], g_zj2[Mcb];
__device__ __align__(16) float g_isp[Mcb], g_isq[Mcb], g_wfac[Mcb], g_scale[Mcb];
__device__ float g_z2[Bq];
__device__ float g_den[Bq];
__device__ float g_dpart[Bq * 256];
__device__ float g_opart[4 * Bq * 512];

// ---------------- helpers ----------------
__device__ __forceinline__ uint32_t smem_u32(const void* p) {
    uint32_t a;
    asm("{ .reg .u64 t; cvta.to.shared.u64 t, %1; cvt.u32.u64 %0, t; }" : "=r"(a) : "l"(p));
    return a;
}
__device__ __forceinline__ void cpa16(uint32_t s, const void* g) {
    asm volatile("{ .reg .u64 gg; cvta.to.global.u64 gg, %1; cp.async.cg.shared.global [%0], [gg], 16; }"
                 :: "r"(s), "l"(g) : "memory");
}
__device__ __forceinline__ void cpa_commit() { asm volatile("cp.async.commit_group;" ::: "memory"); }
__device__ __forceinline__ void cpa_wait0() { asm volatile("cp.async.wait_group 0;" ::: "memory"); }
__device__ __forceinline__ void cpa_wait1() { asm volatile("cp.async.wait_group 1;" ::: "memory"); }

__device__ __forceinline__ void mma_bf16(float* d, const uint32_t* a, const uint32_t* b) {
    asm volatile("mma.sync.aligned.m16n8k16.row.col.f32.bf16.bf16.f32 "
                 "{%0,%1,%2,%3}, {%4,%5,%6,%7}, {%8,%9}, {%0,%1,%2,%3};"
                 : "+f"(d[0]), "+f"(d[1]), "+f"(d[2]), "+f"(d[3])
                 : "r"(a[0]), "r"(a[1]), "r"(a[2]), "r"(a[3]), "r"(b[0]), "r"(b[1]));
}
__device__ __forceinline__ void mma_s8(int* d, const uint32_t* a, const uint32_t* b) {
    asm volatile("mma.sync.aligned.m16n8k32.row.col.s32.s8.s8.s32 "
                 "{%0,%1,%2,%3}, {%4,%5,%6,%7}, {%8,%9}, {%0,%1,%2,%3};"
                 : "+r"(d[0]), "+r"(d[1]), "+r"(d[2]), "+r"(d[3])
                 : "r"(a[0]), "r"(a[1]), "r"(a[2]), "r"(a[3]), "r"(b[0]), "r"(b[1]));
}
__device__ __forceinline__ void ldmx4(uint32_t* r, uint32_t a) {
    asm volatile("ldmatrix.sync.aligned.m8n8.x4.shared.b16 {%0,%1,%2,%3}, [%4];"
                 : "=r"(r[0]), "=r"(r[1]), "=r"(r[2]), "=r"(r[3]) : "r"(a));
}
__device__ __forceinline__ uint32_t swz(uint32_t o) { return o ^ ((o >> 3) & 0x70); }

__device__ __forceinline__ void wsplit(__nv_bfloat16* ph, __nv_bfloat16* pl, float x) {
    __nv_bfloat16 h = __float2bfloat16(x);
    *ph = h;
    *pl = __float2bfloat16(x - __bfloat162float(h));
}
__device__ __forceinline__ void split2w(float x, float y, uint32_t& hw, uint32_t& lw) {
    __nv_bfloat16 hx = __float2bfloat16(x), hy = __float2bfloat16(y);
    __nv_bfloat16 lx = __float2bfloat16(x - __bfloat162float(hx));
    __nv_bfloat16 ly = __float2bfloat16(y - __bfloat162float(hy));
    hw = ((uint32_t)__bfloat16_as_ushort(hy) << 16) | __bfloat16_as_ushort(hx);
    lw = ((uint32_t)__bfloat16_as_ushort(ly) << 16) | __bfloat16_as_ushort(lx);
}
// 2-level int8 quantization of one element into A-layout ([X1|X2]) arrays
__device__ __forceinline__ void qA(int8_t* p1, int8_t* px, int k, float x, float inv) {
    int X1 = __float2int_rn(x * inv);
    X1 = max(-127, min(127, X1));
    float r = x * inv - (float)X1;
    int X2 = __float2int_rn(r * 128.0f);
    X2 = max(-127, min(127, X2));
    p1[k] = (int8_t)X1; px[k] = (int8_t)X1; px[256 + k] = (int8_t)X2;
}
// B-layout: cross array is [Y2 | Y1]
__device__ __forceinline__ void qB(int8_t* p1, int8_t* px, int k, float x, float inv) {
    int X1 = __float2int_rn(x * inv);
    X1 = max(-127, min(127, X1));
    float r = x * inv - (float)X1;
    int X2 = __float2int_rn(r * 128.0f);
    X2 = max(-127, min(127, X2));
    p1[k] = (int8_t)X1; px[k] = (int8_t)X2; px[256 + k] = (int8_t)X1;
}

// ---------------------------------------------------------------------------
// prep_q: normalize d, |z|^2, quantize A operands per-row
// ---------------------------------------------------------------------------
__global__ void prep_q(const float* __restrict__ zr, const float* __restrict__ zi,
                       const float* __restrict__ dr, const float* __restrict__ di) {
    int b = blockIdx.x, t = threadIdx.x;
    __shared__ float s1[128], s2[128];
    float drv = dr[b*Ndim+t], dvv = di[b*Ndim+t];
    float zrv = zr[b*Ndim+t], ziv = zi[b*Ndim+t];
    s1[t] = drv*drv + dvv*dvv;
    s2[t] = zrv*zrv + ziv*ziv;
    __syncthreads();
    for (int o = 64; o > 0; o >>= 1) { if (t < o) { s1[t]+=s1[t+o]; s2[t]+=s2[t+o]; } __syncthreads(); }
    float n = sqrtf(s1[0]); if (n == 0.0f) n = 1.0f;
    float z2v = s2[0];
    float inv = 1.0f / n;
    float ur = drv*inv, ui = dvv*inv;
    __syncthreads();
    // rowmax var0 (z), var1 (u)
    s1[t] = fmaxf(fabsf(zrv), fabsf(ziv));
    s2[t] = fmaxf(fabsf(ur), fabsf(ui));
    __syncthreads();
    for (int o = 64; o > 0; o >>= 1) { if (t < o) { s1[t]=fmaxf(s1[t],s1[t+o]); s2[t]=fmaxf(s2[t],s2[t+o]); } __syncthreads(); }
    float m0 = fmaxf(s1[0], 1e-30f), m1 = fmaxf(s2[0], 1e-30f);
    float i0 = 127.0f / m0, i1 = 127.0f / m1;
    qA(&g_A1[0][b*256], &g_Ax[0][b*512], t,       zrv, i0);
    qA(&g_A1[0][b*256], &g_Ax[0][b*512], 128 + t, ziv, i0);
    qA(&g_A1[1][b*256], &g_Ax[1][b*512], t,       ur,  i1);
    qA(&g_A1[1][b*256], &g_Ax[1][b*512], 128 + t, ui,  i1);
    if (t == 0) {
        g_z2[b] = z2v;
        g_sA[0][b] = m0 / 127.0f;
        g_sA[1][b] = m1 / 127.0f;
    }
}

// ---------------------------------------------------------------------------
// prep_c: normalize d_j, per-code scalars, quantize B operands
// ---------------------------------------------------------------------------
__global__ void prep_c(const float* __restrict__ zjr, const float* __restrict__ zji,
                       const float* __restrict__ djr, const float* __restrict__ dji,
                       const float* __restrict__ alpha, const float* __restrict__ spv,
                       const float* __restrict__ sqv) {
    int m = blockIdx.x, t = threadIdx.x;
    __shared__ float s1[128], s2[128], s3[128];
    float ar = djr[m*Ndim+t], ai = dji[m*Ndim+t];
    s1[t] = ar*ar + ai*ai;
    __syncthreads();
    for (int o = 64; o > 0; o >>= 1) { if (t < o) s1[t]+=s1[t+o]; __syncthreads(); }
    float n = sqrtf(s1[0]); if (n == 0.0f) n = 1.0f;
    float inv = 1.0f / n;
    ar *= inv; ai *= inv;
    float br = zjr[m*Ndim+t], bi = zji[m*Ndim+t];
    __syncthreads();
    // rowmaxes: var0/1 share scale; var2
    s1[t] = fmaxf(fabsf(ar), fabsf(ai));
    s2[t] = fmaxf(fabsf(br), fabsf(bi));
    __syncthreads();
    for (int o = 64; o > 0; o >>= 1) { if (t < o) { s1[t]=fmaxf(s1[t],s1[t+o]); s2[t]=fmaxf(s2[t],s2[t+o]); } __syncthreads(); }
    float m0 = fmaxf(s1[0], 1e-30f), m2 = fmaxf(s2[0], 1e-30f);
    float i0 = 127.0f / m0, i2 = 127.0f / m2;
    qB(&g_B1[0][m*256], &g_Bx[0][m*512], t,       ar,  i0);
    qB(&g_B1[0][m*256], &g_Bx[0][m*512], 128 + t, ai,  i0);
    qB(&g_B1[1][m*256], &g_Bx[1][m*512], t,       -ai, i0);
    qB(&g_B1[1][m*256], &g_Bx[1][m*512], 128 + t, ar,  i0);
    qB(&g_B1[2][m*256], &g_Bx[2][m*512], t,       br,  i2);
    qB(&g_B1[2][m*256], &g_Bx[2][m*512], 128 + t, bi,  i2);
    __syncthreads();
    s1[t] = ar*br + ai*bi;
    s2[t] = ar*bi - ai*br;
    s3[t] = br*br + bi*bi;
    __syncthreads();
    for (int o = 64; o > 0; o >>= 1) {
        if (t < o) { s1[t]+=s1[t+o]; s2[t]+=s2[t+o]; s3[t]+=s3[t+o]; }
        __syncthreads();
    }
    if (t == 0) {
        float a  = fmaxf(alpha[m], TINY);
        float sp = fmaxf(spv[m], TINY);
        float sq = fmaxf(sqv[m], TINY);
        g_cr[m] = s1[0]; g_ci[m] = s2[0]; g_zj2[m] = s3[0];
        g_isp[m] = PI_F / sp;
        g_isq[m] = PI_F / sq;
        g_scale[m] = sqrtf(sp / PI_F);
        g_wfac[m] = a * sqrtf(sp) / PI_F;
        g_sB[0][m] = m0 / 127.0f;
        g_sB[1][m] = m0 / 127.0f;
        g_sB[2][m] = m2 / 127.0f;
    }
}

// Tcat^T[scat][m], hi/lo split.  grid (16, 256), block (32, 8)
__global__ void prep_T(const float* __restrict__ Tre, const float* __restrict__ Tim) {
    __shared__ float tile[32][33];
    int sx = blockIdx.x * 32, my = blockIdx.y * 32;
    int tx = threadIdx.x, ty = threadIdx.y;
    const float* Ts = (sx < Spay) ? Tre : Tim;
    int sl = sx & (Spay - 1);
#pragma unroll
    for (int i = 0; i < 4; i++) {
        int ml = ty + i * 8;
        tile[tx][ml] = Ts[(my + ml) * Spay + sl + tx];
    }
    __syncthreads();
#pragma unroll
    for (int i = 0; i < 4; i++) {
        int srow = sx + ty + i * 8;
        float v = tile[ty + i * 8][tx];
        wsplit(&g_Tth[(size_t)srow * Mcb + my + tx], &g_Ttl[(size_t)srow * Mcb + my + tx], v);
    }
}

// ---------------------------------------------------------------------------
// wkern: int8 2-level mma.sync 5-acc GEMM (128b x 64m) + quadrature epilogue
// 6 chunks of 128 int8-K (2 = P1, 4 = cross), 3-stage cp.async pipeline.
// acc combined: 128*P1 + Pcross, scaled by sA*sB/128 in epilogue.
// ---------------------------------------------------------------------------
#define WA_REG 32768
#define WB_REG 24576
#define WSTG   (WA_REG + WB_REG)   // 57344
#define WSMEM  (3 * WSTG)          // 172032

__global__ __launch_bounds__(256, 1) void wkern() {
    extern __shared__ __align__(16) uint8_t sm[];
    const uint32_t smb = smem_u32(sm);
    const int t = threadIdx.x, wid = t >> 5, lane = t & 31;
    const int mCTA = blockIdx.x, bCTA = blockIdx.y;
    const int wb = wid >> 1, wm = wid & 1;

    int acc[5][2][4][4] = {};

    auto issue = [&](int ch) {
        int s = ch % 3;
        bool cross = (ch >= 2);
        int koff = cross ? (ch - 2) * 128 : ch * 128;
        int stride = cross ? 512 : 256;
        uint32_t dstA = smb + s * WSTG;
        uint32_t dstB = dstA + WA_REG;
#pragma unroll
        for (int i = 0; i < 8; i++) {      // A: 2048 granules of 16B
            int g = i * 256 + t;
            int var = g >> 10, row = (g >> 3) & 127, c16 = g & 7;
            const int8_t* base = cross ? g_Ax[var] : g_A1[var];
            const void* src = base + (size_t)(bCTA*128 + row)*stride + koff + c16*16;
            cpa16(dstA + var*16384 + swz(row*128 + c16*16), src);
        }
#pragma unroll
        for (int i = 0; i < 6; i++) {      // B: 1536 granules
            int g = i * 256 + t;
            int var = g >> 9, row = (g >> 3) & 63, c16 = g & 7;
            const int8_t* base = cross ? g_Bx[var] : g_B1[var];
            const void* src = base + (size_t)(mCTA*64 + row)*stride + koff + c16*16;
            cpa16(dstB + var*8192 + swz(row*128 + c16*16), src);
        }
        cpa_commit();
    };

    const int arow = wb*32 + ((lane >> 3) & 1)*8 + (lane & 7);
    const int ac16 = lane >> 4;
    const int brow_in = ((lane >> 4) ? 8 : 0) + (lane & 7);
    const int bk16 = (lane >> 3) & 1;

    auto compute = [&](int s) {
        uint32_t baseA = smb + s * WSTG;
        uint32_t baseB = baseA + WA_REG;
#pragma unroll
        for (int kt = 0; kt < 4; kt++) {
            uint32_t af[2][2][4];
#pragma unroll
            for (int var = 0; var < 2; var++)
#pragma unroll
                for (int bt = 0; bt < 2; bt++) {
                    uint32_t o = (uint32_t)(arow + bt*16)*128 + (kt*2 + ac16)*16;
                    ldmx4(af[var][bt], baseA + var*16384 + swz(o));
                }
#pragma unroll
            for (int VAR = 0; VAR < 3; VAR++) {
#pragma unroll
                for (int np = 0; np < 2; np++) {
                    uint32_t bf[4];
                    uint32_t o = (uint32_t)((wm*4 + np*2)*8 + brow_in)*128 + (kt*2 + bk16)*16;
                    ldmx4(bf, baseB + VAR*8192 + swz(o));
#pragma unroll
                    for (int h = 0; h < 2; h++) {
                        int nt = np*2 + h;
                        const uint32_t* bsel = &bf[h*2];
                        if (VAR == 0) {
                            mma_s8(acc[0][0][nt], af[0][0], bsel); mma_s8(acc[0][1][nt], af[0][1], bsel);
                            mma_s8(acc[3][0][nt], af[1][0], bsel); mma_s8(acc[3][1][nt], af[1][1], bsel);
                        } else if (VAR == 1) {
                            mma_s8(acc[1][0][nt], af[0][0], bsel); mma_s8(acc[1][1][nt], af[0][1], bsel);
                            mma_s8(acc[4][0][nt], af[1][0], bsel); mma_s8(acc[4][1][nt], af[1][1], bsel);
                        } else {
                            mma_s8(acc[2][0][nt], af[0][0], bsel); mma_s8(acc[2][1][nt], af[0][1], bsel);
                        }
                    }
                }
            }
        }
    };

    issue(0);
    issue(1);
    for (int ch = 0; ch < 6; ch++) {
        if (ch < 5) cpa_wait1(); else cpa_wait0();
        __syncthreads();
        if (ch < 4) issue(ch + 2);
        compute(ch % 3);
        if (ch == 1) {     // fold: acc = 128*P1, cross accumulates on top
            int* p = &acc[0][0][0][0];
#pragma unroll
            for (int i = 0; i < 160; i++) p[i] <<= 7;
        }
    }

    // ---- epilogue ----
    const int mBase = mCTA*64 + wm*32 + ((lane & 3) << 1);
    float2 crv[4], civ[4], zjv[4], ipv[4], iqv[4], wfv[4], scv[4];
    float2 sb0[4], sb1[4], sb2[4];
#pragma unroll
    for (int nt = 0; nt < 4; nt++) {
        int m = mBase + nt*8;
        crv[nt] = *(const float2*)&g_cr[m];   civ[nt] = *(const float2*)&g_ci[m];
        zjv[nt] = *(const float2*)&g_zj2[m];  ipv[nt] = *(const float2*)&g_isp[m];
        iqv[nt] = *(const float2*)&g_isq[m];  wfv[nt] = *(const float2*)&g_wfac[m];
        scv[nt] = *(const float2*)&g_scale[m];
        sb0[nt] = *(const float2*)&g_sB[0][m];
        sb1[nt] = *(const float2*)&g_sB[1][m];
        sb2[nt] = *(const float2*)&g_sB[2][m];
    }
    const int rBase = bCTA*128 + wb*32 + (lane >> 2);

#pragma unroll
    for (int bt = 0; bt < 2; bt++) {
        float rs[2] = {0.0f, 0.0f};
        float wv[4][4];
        float z2v[2], sa0[2], sa1[2];
#pragma unroll
        for (int h = 0; h < 2; h++) {
            int b = rBase + bt*16 + h*8;
            z2v[h] = g_z2[b];
            sa0[h] = g_sA[0][b] * 0.0078125f;
            sa1[h] = g_sA[1][b] * 0.0078125f;
        }
#pragma unroll
        for (int nt = 0; nt < 4; nt++) {
#pragma unroll
            for (int c = 0; c < 4; c++) {
                int h = c >> 1, j = c & 1;
                float cr = j ? crv[nt].y : crv[nt].x;
                float ci = j ? civ[nt].y : civ[nt].x;
                float zj = j ? zjv[nt].y : zjv[nt].x;
                float ip = j ? ipv[nt].y : ipv[nt].x;
                float iq = j ? iqv[nt].y : iqv[nt].x;
                float wf = j ? wfv[nt].y : wfv[nt].x;
                float sc = j ? scv[nt].y : scv[nt].x;
                float b0s = j ? sb0[nt].y : sb0[nt].x;
                float b1s = j ? sb1[nt].y : sb1[nt].x;
                float b2s = j ? sb2[nt].y : sb2[nt].x;
                float a1 = sa0[h] * b0s * (float)acc[0][bt][nt][c];
                float a2 = sa0[h] * b1s * (float)acc[1][bt][nt][c];
                float a3 = sa0[h] * b2s * (float)acc[2][bt][nt][c];
                float a4 = sa1[h] * b0s * (float)acc[3][bt][nt][c];
                float a5 = sa1[h] * b1s * (float)acc[4][bt][nt][c];
                float pr = a1 - cr;
                float pim = a2 - ci;
                float dz2 = z2v[h] + zj - 2.0f * a3;
                float perp2 = fmaxf(dz2 - (pr*pr + pim*pim), 0.0f);
                float align_ = a4*a4 + a5*a5;
                float base = -ip * (pim*pim) - iq * perp2;
                float ssum = 0.0f;
#pragma unroll
                for (int k = 0; k < 8; k++) {
                    float d = pr - GHT[k] * sc;
                    ssum += GHW[k] * __expf(fmaf(-ip * d, d, base));
                }
                float w = wf * align_ * ssum;
                wv[nt][c] = w;
                rs[h] += w;
            }
        }
#pragma unroll
        for (int h = 0; h < 2; h++) {
            float v = rs[h];
            v += __shfl_xor_sync(0xffffffffu, v, 1);
            v += __shfl_xor_sync(0xffffffffu, v, 2);
            if ((lane & 3) == 0)
                g_dpart[(rBase + bt*16 + h*8) * 256 + mCTA*2 + wm] = v;
        }
#pragma unroll
        for (int h = 0; h < 2; h++) {
            size_t rowoff = (size_t)(rBase + bt*16 + h*8) * Mcb;
#pragma unroll
            for (int nt = 0; nt < 4; nt++) {
                uint32_t hw, lw;
                split2w(wv[nt][h*2], wv[nt][h*2 + 1], hw, lw);
                *(uint32_t*)&g_Whi[rowoff + mBase + nt*8] = hw;
                *(uint32_t*)&g_Wlo[rowoff + mBase + nt*8] = lw;
            }
        }
    }
}

// ---------------------------------------------------------------------------
__global__ void denk() {
    int b = blockIdx.x, t = threadIdx.x;
    __shared__ float sh[256];
    sh[t] = g_dpart[b * 256 + t];
    __syncthreads();
    for (int o = 128; o > 0; o >>= 1) { if (t < o) sh[t] += sh[t + o]; __syncthreads(); }
    if (t == 0) g_den[b] = sh[0] + EPST;
}

// ---------------------------------------------------------------------------
// outk: partial out = W @ Tcat. CTA 128b x 128scat, warp tile 32x64.
// Fused {Whi,Wlo,Thi,Tlo} chunk. grid (4 s, 8 b, 4 ksplit) = 128 CTAs, 1 wave.
// ---------------------------------------------------------------------------
#define OTILE 16384
#define OSTG  (4 * OTILE)   // 65536
#define OSMEM (3 * OSTG)    // 196608

__global__ __launch_bounds__(256, 1) void outk() {
    extern __shared__ __align__(16) uint8_t sm[];
    const uint32_t smb = smem_u32(sm);
    const int t = threadIdx.x, wid = t >> 5, lane = t & 31;
    const int sCTA = blockIdx.x, bCTA = blockIdx.y, kz = blockIdx.z;
    const int wb = wid >> 1, ws = wid & 1;
    const int b0 = bCTA * 128, s0 = sCTA * 128;
    const int kbase = kz * 2048;

    float acc[2][8][4] = {};

    auto issue = [&](int ch) {
        int s = ch % 3;
        int k0 = kbase + ch * 64;
        uint32_t dst = smb + s * OSTG;
        const __nv_bfloat16* srcs[4] = { g_Whi, g_Wlo, g_Tth, g_Ttl };
        const int r0[4] = { b0, b0, s0, s0 };
#pragma unroll
        for (int ti = 0; ti < 4; ti++) {
#pragma unroll
            for (int i = 0; i < 4; i++) {   // 1024 granules per tile (128 rows x 8)
                int g = i * 256 + t;
                int row = g >> 3, c16 = g & 7;
                cpa16(dst + ti*OTILE + swz(row*128 + c16*16),
                      srcs[ti] + (size_t)(r0[ti] + row)*Mcb + k0 + c16*8);
            }
        }
        cpa_commit();
    };

    const int arow = wb*32 + ((lane >> 3) & 1)*8 + (lane & 7);
    const int ac16 = lane >> 4;
    const int brow_in = ((lane >> 4) ? 8 : 0) + (lane & 7);
    const int bk16 = (lane >> 3) & 1;

    auto compute = [&](int s) {
        uint32_t base = smb + s * OSTG;
#pragma unroll
        for (int kt = 0; kt < 4; kt++) {
            uint32_t ah[2][4], al[2][4];
#pragma unroll
            for (int bt = 0; bt < 2; bt++) {
                uint32_t oA = (uint32_t)(arow + bt*16)*128 + (kt*2 + ac16)*16;
                ldmx4(ah[bt], base + swz(oA));
                ldmx4(al[bt], base + OTILE + swz(oA));
            }
#pragma unroll
            for (int np = 0; np < 4; np++) {
                uint32_t bh[4], bl[4];
                uint32_t oB = (uint32_t)((ws*8 + np*2)*8 + brow_in)*128 + (kt*2 + bk16)*16;
                ldmx4(bh, base + 2*OTILE + swz(oB));
                ldmx4(bl, base + 3*OTILE + swz(oB));
#pragma unroll
                for (int h = 0; h < 2; h++) {
                    int nt = np*2 + h;
#pragma unroll
                    for (int bt = 0; bt < 2; bt++) {
                        float* a = acc[bt][nt];
                        mma_bf16(a, ah[bt], &bh[h*2]);
                        mma_bf16(a, al[bt], &bh[h*2]);
                        mma_bf16(a, ah[bt], &bl[h*2]);
                    }
                }
            }
        }
    };

    issue(0);
    issue(1);
    for (int ch = 0; ch < 32; ch++) {
        if (ch < 31) cpa_wait1(); else cpa_wait0();
        __syncthreads();
        if (ch < 30) issue(ch + 2);
        compute(ch % 3);
    }

    const int sBase = s0 + ws*64 + ((lane & 3) << 1);
    const int rB = b0 + wb*32 + (lane >> 2);
    float* part = g_opart + (size_t)kz * Bq * 512;
#pragma unroll
    for (int bt = 0; bt < 2; bt++) {
#pragma unroll
        for (int h = 0; h < 2; h++) {
            int b = rB + bt*16 + h*8;
#pragma unroll
            for (int nt = 0; nt < 8; nt++) {
                int scat = sBase + nt*8;
                *(float2*)&part[(size_t)b * 512 + scat] =
                    make_float2(acc[bt][nt][h*2], acc[bt][nt][h*2 + 1]);
            }
        }
    }
}

// ---------------------------------------------------------------------------
// fink: out = (sum of 4 partials) / den, interleave [B,S,2]
// ---------------------------------------------------------------------------
__global__ void fink(float* __restrict__ out) {
    int b = blockIdx.x, t = threadIdx.x;
    float inv = 1.0f / g_den[b];
#pragma unroll
    for (int i = 0; i < 2; i++) {
        int scat = i * 256 + t;
        float v = 0.0f;
#pragma unroll
        for (int kz = 0; kz < 4; kz++)
            v += g_opart[(size_t)kz * Bq * 512 + (size_t)b * 512 + scat];
        v *= inv;
        int c = scat >> 8;
        int sl = scat & (Spay - 1);
        out[((size_t)b * Spay + sl) * 2 + c] = v;
    }
}

// ---------------------------------------------------------------------------
extern "C" void kernel_launch(void* const* d_in, const int* in_sizes, int n_in,
                              void* d_out, int out_size) {
    const float* z_re  = (const float*)d_in[0];
    const float* z_im  = (const float*)d_in[1];
    const float* d_re  = (const float*)d_in[2];
    const float* d_im  = (const float*)d_in[3];
    const float* zj_re = (const float*)d_in[4];
    const float* zj_im = (const float*)d_in[5];
    const float* dj_re = (const float*)d_in[6];
    const float* dj_im = (const float*)d_in[7];
    const float* T_re  = (const float*)d_in[8];
    const float* T_im  = (const float*)d_in[9];
    const float* alpha = (const float*)d_in[10];
    const float* s_par = (const float*)d_in[11];
    const float* s_perp = (const float*)d_in[12];
    float* out = (float*)d_out;

    cudaFuncSetAttribute(wkern, cudaFuncAttributeMaxDynamicSharedMemorySize, WSMEM);
    cudaFuncSetAttribute(outk,  cudaFuncAttributeMaxDynamicSharedMemorySize, OSMEM);

    prep_q<<<Bq, 128>>>(z_re, z_im, d_re, d_im);
    prep_c<<<Mcb, 128>>>(zj_re, zj_im, dj_re, dj_im, alpha, s_par, s_perp);
    prep_T<<<dim3(512 / 32, Mcb / 32), dim3(32, 8)>>>(T_re, T_im);
    wkern<<<dim3(Mcb / 64, Bq / 128), 256, WSMEM>>>();
    denk<<<Bq, 256>>>();
    outk<<<dim3(4, 8, 4), 256, OSMEM>>>();
    fink<<<Bq, 256>>>(out);
}

// round 7
// speedup vs baseline: 2.0207x; 2.0207x over previous
#include <cuda_runtime.h>
#include <cuda_bf16.h>
#include <math.h>
#include <stdint.h>

#define Bq   1024
#define Ndim 128
#define Mcb  8192
#define Spay 256
#define EPST 1e-3f
#define PI_F 3.14159265358979323846f
#define TINY 1.17549435e-38f

__constant__ float GHT[8] = {
    -2.9306374202572440f, -1.9816567566958429f, -1.1571937124467802f, -0.3811869902073221f,
     0.3811869902073221f,  1.1571937124467802f,  1.9816567566958429f,  2.9306374202572440f};
__constant__ float GHW[8] = {
    1.9960407221136762e-04f, 1.7077983007413475e-02f, 2.0780232581489188e-01f, 6.6114701255824130e-01f,
    6.6114701255824130e-01f, 2.0780232581489188e-01f, 1.7077983007413475e-02f, 1.9960407221136762e-04f};

// ---------------- scratch (row-major simple layouts only) ----------------
__device__ __align__(16) __nv_bfloat16 g_Ah[2][Bq * 256];   // A var 0=[zr|zi], 1=[ur|ui]
__device__ __align__(16) __nv_bfloat16 g_Al[2][Bq * 256];
__device__ __align__(16) __nv_bfloat16 g_Bh[3][Mcb * 256];  // B var 0=[ar|ai], 1=[-ai|ar], 2=[br|bi]
__device__ __align__(16) __nv_bfloat16 g_Bl[3][Mcb * 256];
__device__ __align__(16) __nv_bfloat16 g_Tth[512 * Mcb];    // Tcat^T [scat][m]
__device__ __align__(16) __nv_bfloat16 g_Ttl[512 * Mcb];
__device__ __align__(16) __nv_bfloat16 g_Whi[(size_t)Bq * Mcb];  // W [b][m]
__device__ __align__(16) __nv_bfloat16 g_Wlo[(size_t)Bq * Mcb];
__device__ __align__(16) float g_cr[Mcb], g_ci[Mcb], g_zj2[Mcb];
__device__ __align__(16) float g_isp[Mcb], g_isq[Mcb], g_wfac[Mcb], g_scale[Mcb];
__device__ float g_z2[Bq];
__device__ float g_den[Bq];
__device__ float g_dpart[Bq * 512];
__device__ float g_opart[2 * Bq * 512];   // K-split partials of out GEMM

// ---------------- helpers ----------------
__device__ __forceinline__ uint32_t smem_u32(const void* p) {
    uint32_t a;
    asm("{ .reg .u64 t; cvta.to.shared.u64 t, %1; cvt.u32.u64 %0, t; }" : "=r"(a) : "l"(p));
    return a;
}
__device__ __forceinline__ void cpa16(uint32_t s, const void* g) {
    asm volatile("{ .reg .u64 gg; cvta.to.global.u64 gg, %1; cp.async.cg.shared.global [%0], [gg], 16; }"
                 :: "r"(s), "l"(g) : "memory");
}
__device__ __forceinline__ void cpa_commit() { asm volatile("cp.async.commit_group;" ::: "memory"); }
__device__ __forceinline__ void cpa_wait0() { asm volatile("cp.async.wait_group 0;" ::: "memory"); }
__device__ __forceinline__ void cpa_wait1() { asm volatile("cp.async.wait_group 1;" ::: "memory"); }

__device__ __forceinline__ void mma_bf16(float* d, const uint32_t* a, const uint32_t* b) {
    asm volatile("mma.sync.aligned.m16n8k16.row.col.f32.bf16.bf16.f32 "
                 "{%0,%1,%2,%3}, {%4,%5,%6,%7}, {%8,%9}, {%0,%1,%2,%3};"
                 : "+f"(d[0]), "+f"(d[1]), "+f"(d[2]), "+f"(d[3])
                 : "r"(a[0]), "r"(a[1]), "r"(a[2]), "r"(a[3]), "r"(b[0]), "r"(b[1]));
}
__device__ __forceinline__ void ldmx4(uint32_t* r, uint32_t a) {
    asm volatile("ldmatrix.sync.aligned.m8n8.x4.shared.b16 {%0,%1,%2,%3}, [%4];"
                 : "=r"(r[0]), "=r"(r[1]), "=r"(r[2]), "=r"(r[3]) : "r"(a));
}
__device__ __forceinline__ uint32_t swz(uint32_t o) { return o ^ ((o >> 3) & 0x70); }

__device__ __forceinline__ void wsplit(__nv_bfloat16* ph, __nv_bfloat16* pl, float x) {
    __nv_bfloat16 h = __float2bfloat16(x);
    *ph = h;
    *pl = __float2bfloat16(x - __bfloat162float(h));
}
__device__ __forceinline__ void split2w(float x, float y, uint32_t& hw, uint32_t& lw) {
    __nv_bfloat16 hx = __float2bfloat16(x), hy = __float2bfloat16(y);
    __nv_bfloat16 lx = __float2bfloat16(x - __bfloat162float(hx));
    __nv_bfloat16 ly = __float2bfloat16(y - __bfloat162float(hy));
    hw = ((uint32_t)__bfloat16_as_ushort(hy) << 16) | __bfloat16_as_ushort(hx);
    lw = ((uint32_t)__bfloat16_as_ushort(ly) << 16) | __bfloat16_as_ushort(lx);
}

// ---------------------------------------------------------------------------
// prep kernels
// ---------------------------------------------------------------------------
__global__ void prep_q(const float* __restrict__ zr, const float* __restrict__ zi,
                       const float* __restrict__ dr, const float* __restrict__ di) {
    int b = blockIdx.x, t = threadIdx.x;
    __shared__ float s1[128], s2[128];
    float drv = dr[b*Ndim+t], dvv = di[b*Ndim+t];
    float zrv = zr[b*Ndim+t], ziv = zi[b*Ndim+t];
    s1[t] = drv*drv + dvv*dvv;
    s2[t] = zrv*zrv + ziv*ziv;
    __syncthreads();
    for (int o = 64; o > 0; o >>= 1) { if (t < o) { s1[t]+=s1[t+o]; s2[t]+=s2[t+o]; } __syncthreads(); }
    float n = sqrtf(s1[0]); if (n == 0.0f) n = 1.0f;
    float inv = 1.0f / n;
    float ur = drv*inv, ui = dvv*inv;
    wsplit(&g_Ah[0][b*256+t],     &g_Al[0][b*256+t],     zrv);
    wsplit(&g_Ah[0][b*256+128+t], &g_Al[0][b*256+128+t], ziv);
    wsplit(&g_Ah[1][b*256+t],     &g_Al[1][b*256+t],     ur);
    wsplit(&g_Ah[1][b*256+128+t], &g_Al[1][b*256+128+t], ui);
    if (t == 0) g_z2[b] = s2[0];
}

__global__ void prep_c(const float* __restrict__ zjr, const float* __restrict__ zji,
                       const float* __restrict__ djr, const float* __restrict__ dji,
                       const float* __restrict__ alpha, const float* __restrict__ spv,
                       const float* __restrict__ sqv) {
    int m = blockIdx.x, t = threadIdx.x;
    __shared__ float s1[128], s2[128], s3[128];
    float ar = djr[m*Ndim+t], ai = dji[m*Ndim+t];
    s1[t] = ar*ar + ai*ai;
    __syncthreads();
    for (int o = 64; o > 0; o >>= 1) { if (t < o) s1[t]+=s1[t+o]; __syncthreads(); }
    float n = sqrtf(s1[0]); if (n == 0.0f) n = 1.0f;
    float inv = 1.0f / n;
    ar *= inv; ai *= inv;
    float br = zjr[m*Ndim+t], bi = zji[m*Ndim+t];
    wsplit(&g_Bh[0][m*256+t],     &g_Bl[0][m*256+t],     ar);
    wsplit(&g_Bh[0][m*256+128+t], &g_Bl[0][m*256+128+t], ai);
    wsplit(&g_Bh[1][m*256+t],     &g_Bl[1][m*256+t],     -ai);
    wsplit(&g_Bh[1][m*256+128+t], &g_Bl[1][m*256+128+t], ar);
    wsplit(&g_Bh[2][m*256+t],     &g_Bl[2][m*256+t],     br);
    wsplit(&g_Bh[2][m*256+128+t], &g_Bl[2][m*256+128+t], bi);
    __syncthreads();
    s1[t] = ar*br + ai*bi;
    s2[t] = ar*bi - ai*br;
    s3[t] = br*br + bi*bi;
    __syncthreads();
    for (int o = 64; o > 0; o >>= 1) {
        if (t < o) { s1[t]+=s1[t+o]; s2[t]+=s2[t+o]; s3[t]+=s3[t+o]; }
        __syncthreads();
    }
    if (t == 0) {
        float a  = fmaxf(alpha[m], TINY);
        float sp = fmaxf(spv[m], TINY);
        float sq = fmaxf(sqv[m], TINY);
        g_cr[m] = s1[0]; g_ci[m] = s2[0]; g_zj2[m] = s3[0];
        g_isp[m] = PI_F / sp;
        g_isq[m] = PI_F / sq;
        g_scale[m] = sqrtf(sp / PI_F);
        g_wfac[m] = a * sqrtf(sp) / PI_F;
    }
}

// Tcat^T[scat][m], hi/lo split.  grid (16, 256), block (32, 8)
__global__ void prep_T(const float* __restrict__ Tre, const float* __restrict__ Tim) {
    __shared__ float tile[32][33];
    int sx = blockIdx.x * 32, my = blockIdx.y * 32;
    int tx = threadIdx.x, ty = threadIdx.y;
    const float* Ts = (sx < Spay) ? Tre : Tim;
    int sl = sx & (Spay - 1);
#pragma unroll
    for (int i = 0; i < 4; i++) {
        int ml = ty + i * 8;
        tile[tx][ml] = Ts[(my + ml) * Spay + sl + tx];
    }
    __syncthreads();
#pragma unroll
    for (int i = 0; i < 4; i++) {
        int srow = sx + ty + i * 8;
        float v = tile[ty + i * 8][tx];
        wsplit(&g_Tth[(size_t)srow * Mcb + my + tx], &g_Ttl[(size_t)srow * Mcb + my + tx], v);
    }
}

// ---------------------------------------------------------------------------
// wkern: split-bf16 mma.sync 5-acc GEMM (128b x 64m), 512 threads / 16 warps,
// warp tile 32(b) x 16(m). 3-stage cp.async pipeline.
// ---------------------------------------------------------------------------
#define WA_REG 32768
#define WB_REG 24576
#define WSTG   (WA_REG + WB_REG)   // 57344
#define WSMEM  (3 * WSTG)          // 172032

__global__ __launch_bounds__(512, 1) void wkern() {
    extern __shared__ __align__(16) uint8_t sm[];
    const uint32_t smb = smem_u32(sm);
    const int t = threadIdx.x, wid = t >> 5, lane = t & 31;
    const int mCTA = blockIdx.x, bCTA = blockIdx.y;
    const int wb = wid >> 2, wm = wid & 3;   // 4 b-groups x 4 m-groups

    float acc[5][2][2][4] = {};   // [prod][bt(16 rows)][nt(8 cols)][frag]

    auto issue = [&](int ch) {
        int s = ch % 3;
        int grp = ch >> 2;                 // 0: hh, 1: lo(A)*hi(B), 2: hi(A)*lo(B)
        int k0 = (ch & 3) * 64;
        uint32_t dstA = smb + s * WSTG;
        uint32_t dstB = dstA + WA_REG;
        const __nv_bfloat16* A0 = (grp == 1) ? g_Al[0] : g_Ah[0];
        const __nv_bfloat16* A1 = (grp == 1) ? g_Al[1] : g_Ah[1];
        const __nv_bfloat16* B0 = (grp == 2) ? g_Bl[0] : g_Bh[0];
        const __nv_bfloat16* B1 = (grp == 2) ? g_Bl[1] : g_Bh[1];
        const __nv_bfloat16* B2 = (grp == 2) ? g_Bl[2] : g_Bh[2];
        const __nv_bfloat16* As[2] = {A0, A1};
        const __nv_bfloat16* Bs[3] = {B0, B1, B2};
#pragma unroll
        for (int i = 0; i < 4; i++) {      // A: 2048 granules of 16B
            int g = i * 512 + t;
            int var = g >> 10, row = (g >> 3) & 127, c16 = g & 7;
            const void* src = As[var] + (size_t)(bCTA*128 + row)*256 + k0 + c16*8;
            cpa16(dstA + var*16384 + swz(row*128 + c16*16), src);
        }
#pragma unroll
        for (int i = 0; i < 3; i++) {      // B: 1536 granules
            int g = i * 512 + t;
            int var = g >> 9, row = (g >> 3) & 63, c16 = g & 7;
            const void* src = Bs[var] + (size_t)(mCTA*64 + row)*256 + k0 + c16*8;
            cpa16(dstB + var*8192 + swz(row*128 + c16*16), src);
        }
        cpa_commit();
    };

    // ldmatrix per-lane row components
    const int arow = wb*32 + ((lane >> 3) & 1)*8 + (lane & 7);   // + bt*16
    const int ac16 = lane >> 4;                                   // + kt*2
    const int brow_in = ((lane >> 4) ? 8 : 0) + (lane & 7);       // nt parity*8 + row
    const int bk16 = (lane >> 3) & 1;                             // + kt*2

    auto compute = [&](int s) {
        uint32_t baseA = smb + s * WSTG;
        uint32_t baseB = baseA + WA_REG;
#pragma unroll
        for (int kt = 0; kt < 4; kt++) {
            uint32_t af[2][2][4];
#pragma unroll
            for (int var = 0; var < 2; var++)
#pragma unroll
                for (int bt = 0; bt < 2; bt++) {
                    uint32_t o = (uint32_t)(arow + bt*16)*128 + (kt*2 + ac16)*16;
                    ldmx4(af[var][bt], baseA + var*16384 + swz(o));
                }
#pragma unroll
            for (int VAR = 0; VAR < 3; VAR++) {
                uint32_t bf[4];
                uint32_t o = (uint32_t)(wm*16 + brow_in)*128 + (kt*2 + bk16)*16;
                ldmx4(bf, baseB + VAR*8192 + swz(o));
#pragma unroll
                for (int h = 0; h < 2; h++) {
                    const uint32_t* bsel = &bf[h*2];
                    if (VAR == 0) {
                        mma_bf16(acc[0][0][h], af[0][0], bsel); mma_bf16(acc[0][1][h], af[0][1], bsel);
                        mma_bf16(acc[3][0][h], af[1][0], bsel); mma_bf16(acc[3][1][h], af[1][1], bsel);
                    } else if (VAR == 1) {
                        mma_bf16(acc[1][0][h], af[0][0], bsel); mma_bf16(acc[1][1][h], af[0][1], bsel);
                        mma_bf16(acc[4][0][h], af[1][0], bsel); mma_bf16(acc[4][1][h], af[1][1], bsel);
                    } else {
                        mma_bf16(acc[2][0][h], af[0][0], bsel); mma_bf16(acc[2][1][h], af[0][1], bsel);
                    }
                }
            }
        }
    };

    issue(0);
    issue(1);
    for (int ch = 0; ch < 12; ch++) {
        if (ch < 11) cpa_wait1(); else cpa_wait0();
        __syncthreads();
        if (ch < 10) issue(ch + 2);
        compute(ch % 3);
    }

    // ---- epilogue (D frag: row = lane/4 + (c>>1)*8, col = 2*(lane%4) + (c&1)) ----
    const int mBase = mCTA*64 + wm*16 + ((lane & 3) << 1);
    float2 crv[2], civ[2], zjv[2], ipv[2], iqv[2], wfv[2], scv[2];
#pragma unroll
    for (int nt = 0; nt < 2; nt++) {
        int m = mBase + nt*8;
        crv[nt] = *(const float2*)&g_cr[m];   civ[nt] = *(const float2*)&g_ci[m];
        zjv[nt] = *(const float2*)&g_zj2[m];  ipv[nt] = *(const float2*)&g_isp[m];
        iqv[nt] = *(const float2*)&g_isq[m];  wfv[nt] = *(const float2*)&g_wfac[m];
        scv[nt] = *(const float2*)&g_scale[m];
    }
    const int rBase = bCTA*128 + wb*32 + (lane >> 2);

#pragma unroll
    for (int bt = 0; bt < 2; bt++) {
        float rs[2] = {0.0f, 0.0f};
        float wv[2][4];
        float z2v[2] = { g_z2[rBase + bt*16], g_z2[rBase + bt*16 + 8] };
#pragma unroll
        for (int nt = 0; nt < 2; nt++) {
#pragma unroll
            for (int c = 0; c < 4; c++) {
                int h = c >> 1, j = c & 1;
                float cr = j ? crv[nt].y : crv[nt].x;
                float ci = j ? civ[nt].y : civ[nt].x;
                float zj = j ? zjv[nt].y : zjv[nt].x;
                float ip = j ? ipv[nt].y : ipv[nt].x;
                float iq = j ? iqv[nt].y : iqv[nt].x;
                float wf = j ? wfv[nt].y : wfv[nt].x;
                float sc = j ? scv[nt].y : scv[nt].x;
                float a1 = acc[0][bt][nt][c], a2 = acc[1][bt][nt][c];
                float a3 = acc[2][bt][nt][c], a4 = acc[3][bt][nt][c], a5 = acc[4][bt][nt][c];
                float pr = a1 - cr;
                float pim = a2 - ci;
                float dz2 = z2v[h] + zj - 2.0f * a3;
                float perp2 = fmaxf(dz2 - (pr*pr + pim*pim), 0.0f);
                float align_ = a4*a4 + a5*a5;
                float base = -ip * (pim*pim) - iq * perp2;
                float ssum = 0.0f;
#pragma unroll
                for (int k = 0; k < 8; k++) {
                    float d = pr - GHT[k] * sc;
                    ssum += GHW[k] * __expf(fmaf(-ip * d, d, base));
                }
                float w = wf * align_ * ssum;
                wv[nt][c] = w;
                rs[h] += w;
            }
        }
#pragma unroll
        for (int h = 0; h < 2; h++) {
            float v = rs[h];
            v += __shfl_xor_sync(0xffffffffu, v, 1);
            v += __shfl_xor_sync(0xffffffffu, v, 2);
            if ((lane & 3) == 0)
                g_dpart[(rBase + bt*16 + h*8) * 512 + mCTA*4 + wm] = v;
        }
#pragma unroll
        for (int h = 0; h < 2; h++) {
            size_t rowoff = (size_t)(rBase + bt*16 + h*8) * Mcb;
#pragma unroll
            for (int nt = 0; nt < 2; nt++) {
                uint32_t hw, lw;
                split2w(wv[nt][h*2], wv[nt][h*2 + 1], hw, lw);
                *(uint32_t*)&g_Whi[rowoff + mBase + nt*8] = hw;
                *(uint32_t*)&g_Wlo[rowoff + mBase + nt*8] = lw;
            }
        }
    }
}

// ---------------------------------------------------------------------------
__global__ void denk() {
    int b = blockIdx.x, t = threadIdx.x;
    __shared__ float sh[256];
    sh[t] = g_dpart[b * 512 + t] + g_dpart[b * 512 + 256 + t];
    __syncthreads();
    for (int o = 128; o > 0; o >>= 1) { if (t < o) sh[t] += sh[t + o]; __syncthreads(); }
    if (t == 0) g_den[b] = sh[0] + EPST;
}

// ---------------------------------------------------------------------------
// outk: partial out = W @ Tcat over a K-split. CTA 64b x 64scat.
// Fused chunk: {Whi, Wlo, Thi, Tlo} loaded once, 3 split products computed.
// grid (8 s, 16 b, 2 ksplit), 3-stage pipeline, occ 2.
// ---------------------------------------------------------------------------
#define OTILE 8192
#define OSTG  (4 * OTILE)   // 32768
#define OSMEM (3 * OSTG)    // 98304

__global__ __launch_bounds__(256, 2) void outk() {
    extern __shared__ __align__(16) uint8_t sm[];
    const uint32_t smb = smem_u32(sm);
    const int t = threadIdx.x, wid = t >> 5, lane = t & 31;
    const int sCTA = blockIdx.x, bCTA = blockIdx.y, kz = blockIdx.z;
    const int wb = wid >> 1, ws = wid & 1;
    const int b0 = bCTA * 64, s0 = sCTA * 64;
    const int kbase = kz * 4096;

    float acc[4][4] = {};

    auto issue = [&](int ch) {
        int s = ch % 3;
        int k0 = kbase + ch * 64;
        uint32_t dst = smb + s * OSTG;
        const __nv_bfloat16* srcs[4] = { g_Whi, g_Wlo, g_Tth, g_Ttl };
        const int r0[4] = { b0, b0, s0, s0 };
#pragma unroll
        for (int ti = 0; ti < 4; ti++) {
#pragma unroll
            for (int i = 0; i < 2; i++) {   // 512 granules per tile
                int g = i * 256 + t;
                int row = g >> 3, c16 = g & 7;
                cpa16(dst + ti*OTILE + swz(row*128 + c16*16),
                      srcs[ti] + (size_t)(r0[ti] + row)*Mcb + k0 + c16*8);
            }
        }
        cpa_commit();
    };

    const int arow = wb*16 + ((lane >> 3) & 1)*8 + (lane & 7);
    const int ac16 = lane >> 4;
    const int brow_in = ((lane >> 4) ? 8 : 0) + (lane & 7);
    const int bk16 = (lane >> 3) & 1;

    auto compute = [&](int s) {
        uint32_t base = smb + s * OSTG;
#pragma unroll
        for (int kt = 0; kt < 4; kt++) {
            uint32_t ah[4], al[4];
            uint32_t oA = (uint32_t)arow*128 + (kt*2 + ac16)*16;
            ldmx4(ah, base + swz(oA));
            ldmx4(al, base + OTILE + swz(oA));
#pragma unroll
            for (int np = 0; np < 2; np++) {
                uint32_t bh[4], bl[4];
                uint32_t oB = (uint32_t)((ws*4 + np*2)*8 + brow_in)*128 + (kt*2 + bk16)*16;
                ldmx4(bh, base + 2*OTILE + swz(oB));
                ldmx4(bl, base + 3*OTILE + swz(oB));
#pragma unroll
                for (int h = 0; h < 2; h++) {
                    float* a = acc[np*2 + h];
                    mma_bf16(a, ah, &bh[h*2]);
                    mma_bf16(a, al, &bh[h*2]);
                    mma_bf16(a, ah, &bl[h*2]);
                }
            }
        }
    };

    issue(0);
    issue(1);
    for (int ch = 0; ch < 64; ch++) {
        if (ch < 63) cpa_wait1(); else cpa_wait0();
        __syncthreads();
        if (ch < 62) issue(ch + 2);
        compute(ch % 3);
    }

    const int sBase = s0 + ws*32 + ((lane & 3) << 1);
    const int rB = b0 + wb*16 + (lane >> 2);
    float* part = g_opart + (size_t)kz * Bq * 512;
#pragma unroll
    for (int h = 0; h < 2; h++) {
        int b = rB + h*8;
#pragma unroll
        for (int nt = 0; nt < 4; nt++) {
            int scat = sBase + nt*8;
            *(float2*)&part[(size_t)b * 512 + scat] =
                make_float2(acc[nt][h*2], acc[nt][h*2 + 1]);
        }
    }
}

// ---------------------------------------------------------------------------
// fink: out = (part0 + part1) / den, interleave [B,S,2]
// ---------------------------------------------------------------------------
__global__ void fink(float* __restrict__ out) {
    int b = blockIdx.x, t = threadIdx.x;
    float inv = 1.0f / g_den[b];
#pragma unroll
    for (int i = 0; i < 2; i++) {
        int scat = i * 256 + t;
        float v = (g_opart[(size_t)b * 512 + scat] +
                   g_opart[(size_t)(Bq + b) * 512 + scat]) * inv;
        int c = scat >> 8;
        int sl = scat & (Spay - 1);
        out[((size_t)b * Spay + sl) * 2 + c] = v;
    }
}

// ---------------------------------------------------------------------------
extern "C" void kernel_launch(void* const* d_in, const int* in_sizes, int n_in,
                              void* d_out, int out_size) {
    const float* z_re  = (const float*)d_in[0];
    const float* z_im  = (const float*)d_in[1];
    const float* d_re  = (const float*)d_in[2];
    const float* d_im  = (const float*)d_in[3];
    const float* zj_re = (const float*)d_in[4];
    const float* zj_im = (const float*)d_in[5];
    const float* dj_re = (const float*)d_in[6];
    const float* dj_im = (const float*)d_in[7];
    const float* T_re  = (const float*)d_in[8];
    const float* T_im  = (const float*)d_in[9];
    const float* alpha = (const float*)d_in[10];
    const float* s_par = (const float*)d_in[11];
    const float* s_perp = (const float*)d_in[12];
    float* out = (float*)d_out;

    cudaFuncSetAttribute(wkern, cudaFuncAttributeMaxDynamicSharedMemorySize, WSMEM);
    cudaFuncSetAttribute(outk,  cudaFuncAttributeMaxDynamicSharedMemorySize, OSMEM);

    prep_q<<<Bq, 128>>>(z_re, z_im, d_re, d_im);
    prep_c<<<Mcb, 128>>>(zj_re, zj_im, dj_re, dj_im, alpha, s_par, s_perp);
    prep_T<<<dim3(512 / 32, Mcb / 32), dim3(32, 8)>>>(T_re, T_im);
    wkern<<<dim3(Mcb / 64, Bq / 128), 512, WSMEM>>>();
    denk<<<Bq, 256>>>();
    outk<<<dim3(8, 16, 2), 256, OSMEM>>>();
    fink<<<Bq, 256>>>(out);
}

// round 9
// speedup vs baseline: 2.3588x; 1.1673x over previous
#include <cuda_runtime.h>
#include <cuda_fp16.h>
#include <math.h>
#include <stdint.h>

#define Bq   1024
#define Ndim 128
#define Mcb  8192
#define Spay 256
#define EPST 1e-3f
#define PI_F 3.14159265358979323846f
#define TINY 1.17549435e-38f

__constant__ float GHT[8] = {
    -2.9306374202572440f, -1.9816567566958429f, -1.1571937124467802f, -0.3811869902073221f,
     0.3811869902073221f,  1.1571937124467802f,  1.9816567566958429f,  2.9306374202572440f};
__constant__ float GHW[8] = {
    1.9960407221136762e-04f, 1.7077983007413475e-02f, 2.0780232581489188e-01f, 6.6114701255824130e-01f,
    6.6114701255824130e-01f, 2.0780232581489188e-01f, 1.7077983007413475e-02f, 1.9960407221136762e-04f};

// ---------------- scratch (fp16 hi/lo splits, row-major) ----------------
__device__ __align__(16) __half g_Ah[2][Bq * 256];   // A var 0=[zr|zi], 1=[ur|ui]
__device__ __align__(16) __half g_Al[2][Bq * 256];
__device__ __align__(16) __half g_Bh[3][Mcb * 256];  // B var 0=[ar|ai], 1=[-ai|ar], 2=[br|bi]
__device__ __align__(16) __half g_Bl[3][Mcb * 256];
__device__ __align__(16) __half g_Tth[512 * Mcb];    // Tcat^T [scat][m]
__device__ __align__(16) __half g_Ttl[512 * Mcb];
__device__ __align__(16) __half g_Whi[(size_t)Bq * Mcb];  // W [b][m]
__device__ __align__(16) __half g_Wlo[(size_t)Bq * Mcb];
__device__ __align__(16) float g_cr[Mcb], g_ci[Mcb], g_zj2[Mcb];
__device__ __align__(16) float g_isp[Mcb], g_isq[Mcb], g_wfac[Mcb], g_scale[Mcb];
__device__ float g_z2[Bq];
__device__ float g_den[Bq];
__device__ float g_dpart[Bq * 512];
__device__ float g_opart[2 * Bq * 512];

// ---------------- helpers ----------------
__device__ __forceinline__ uint32_t smem_u32(const void* p) {
    uint32_t a;
    asm("{ .reg .u64 t; cvta.to.shared.u64 t, %1; cvt.u32.u64 %0, t; }" : "=r"(a) : "l"(p));
    return a;
}
__device__ __forceinline__ void cpa16(uint32_t s, const void* g) {
    asm volatile("{ .reg .u64 gg; cvta.to.global.u64 gg, %1; cp.async.cg.shared.global [%0], [gg], 16; }"
                 :: "r"(s), "l"(g) : "memory");
}
__device__ __forceinline__ void cpa_commit() { asm volatile("cp.async.commit_group;" ::: "memory"); }
__device__ __forceinline__ void cpa_wait0() { asm volatile("cp.async.wait_group 0;" ::: "memory"); }
__device__ __forceinline__ void cpa_wait1() { asm volatile("cp.async.wait_group 1;" ::: "memory"); }

__device__ __forceinline__ void mma_f16(float* d, const uint32_t* a, const uint32_t* b) {
    asm volatile("mma.sync.aligned.m16n8k16.row.col.f32.f16.f16.f32 "
                 "{%0,%1,%2,%3}, {%4,%5,%6,%7}, {%8,%9}, {%0,%1,%2,%3};"
                 : "+f"(d[0]), "+f"(d[1]), "+f"(d[2]), "+f"(d[3])
                 : "r"(a[0]), "r"(a[1]), "r"(a[2]), "r"(a[3]), "r"(b[0]), "r"(b[1]));
}
__device__ __forceinline__ void ldmx4(uint32_t* r, uint32_t a) {
    asm volatile("ldmatrix.sync.aligned.m8n8.x4.shared.b16 {%0,%1,%2,%3}, [%4];"
                 : "=r"(r[0]), "=r"(r[1]), "=r"(r[2]), "=r"(r[3]) : "r"(a));
}
__device__ __forceinline__ uint32_t swz(uint32_t o) { return o ^ ((o >> 3) & 0x70); }

__device__ __forceinline__ void hsplit(__half* ph, __half* pl, float x) {
    __half h = __float2half_rn(x);
    *ph = h;
    *pl = __float2half_rn(x - __half2float(h));
}
__device__ __forceinline__ void split2h(float x, float y, uint32_t& hw, uint32_t& lw) {
    __half hx = __float2half_rn(x), hy = __float2half_rn(y);
    __half lx = __float2half_rn(x - __half2float(hx));
    __half ly = __float2half_rn(y - __half2float(hy));
    hw = ((uint32_t)__half_as_ushort(hy) << 16) | __half_as_ushort(hx);
    lw = ((uint32_t)__half_as_ushort(ly) << 16) | __half_as_ushort(lx);
}

// ---------------------------------------------------------------------------
// prep kernels
// ---------------------------------------------------------------------------
__global__ void prep_q(const float* __restrict__ zr, const float* __restrict__ zi,
                       const float* __restrict__ dr, const float* __restrict__ di) {
    int b = blockIdx.x, t = threadIdx.x;
    __shared__ float s1[128], s2[128];
    float drv = dr[b*Ndim+t], dvv = di[b*Ndim+t];
    float zrv = zr[b*Ndim+t], ziv = zi[b*Ndim+t];
    s1[t] = drv*drv + dvv*dvv;
    s2[t] = zrv*zrv + ziv*ziv;
    __syncthreads();
    for (int o = 64; o > 0; o >>= 1) { if (t < o) { s1[t]+=s1[t+o]; s2[t]+=s2[t+o]; } __syncthreads(); }
    float n = sqrtf(s1[0]); if (n == 0.0f) n = 1.0f;
    float inv = 1.0f / n;
    float ur = drv*inv, ui = dvv*inv;
    hsplit(&g_Ah[0][b*256+t],     &g_Al[0][b*256+t],     zrv);
    hsplit(&g_Ah[0][b*256+128+t], &g_Al[0][b*256+128+t], ziv);
    hsplit(&g_Ah[1][b*256+t],     &g_Al[1][b*256+t],     ur);
    hsplit(&g_Ah[1][b*256+128+t], &g_Al[1][b*256+128+t], ui);
    if (t == 0) g_z2[b] = s2[0];
}

__global__ void prep_c(const float* __restrict__ zjr, const float* __restrict__ zji,
                       const float* __restrict__ djr, const float* __restrict__ dji,
                       const float* __restrict__ alpha, const float* __restrict__ spv,
                       const float* __restrict__ sqv) {
    int m = blockIdx.x, t = threadIdx.x;
    __shared__ float s1[128], s2[128], s3[128];
    float ar = djr[m*Ndim+t], ai = dji[m*Ndim+t];
    s1[t] = ar*ar + ai*ai;
    __syncthreads();
    for (int o = 64; o > 0; o >>= 1) { if (t < o) s1[t]+=s1[t+o]; __syncthreads(); }
    float n = sqrtf(s1[0]); if (n == 0.0f) n = 1.0f;
    float inv = 1.0f / n;
    ar *= inv; ai *= inv;
    float br = zjr[m*Ndim+t], bi = zji[m*Ndim+t];
    hsplit(&g_Bh[0][m*256+t],     &g_Bl[0][m*256+t],     ar);
    hsplit(&g_Bh[0][m*256+128+t], &g_Bl[0][m*256+128+t], ai);
    hsplit(&g_Bh[1][m*256+t],     &g_Bl[1][m*256+t],     -ai);
    hsplit(&g_Bh[1][m*256+128+t], &g_Bl[1][m*256+128+t], ar);
    hsplit(&g_Bh[2][m*256+t],     &g_Bl[2][m*256+t],     br);
    hsplit(&g_Bh[2][m*256+128+t], &g_Bl[2][m*256+128+t], bi);
    __syncthreads();
    s1[t] = ar*br + ai*bi;
    s2[t] = ar*bi - ai*br;
    s3[t] = br*br + bi*bi;
    __syncthreads();
    for (int o = 64; o > 0; o >>= 1) {
        if (t < o) { s1[t]+=s1[t+o]; s2[t]+=s2[t+o]; s3[t]+=s3[t+o]; }
        __syncthreads();
    }
    if (t == 0) {
        float a  = fmaxf(alpha[m], TINY);
        float sp = fmaxf(spv[m], TINY);
        float sq = fmaxf(sqv[m], TINY);
        g_cr[m] = s1[0]; g_ci[m] = s2[0]; g_zj2[m] = s3[0];
        g_isp[m] = PI_F / sp;
        g_isq[m] = PI_F / sq;
        g_scale[m] = sqrtf(sp / PI_F);
        g_wfac[m] = a * sqrtf(sp) / PI_F;
    }
}

// Tcat^T[scat][m], hi/lo split.  grid (16, 256), block (32, 8)
__global__ void prep_T(const float* __restrict__ Tre, const float* __restrict__ Tim) {
    __shared__ float tile[32][33];
    int sx = blockIdx.x * 32, my = blockIdx.y * 32;
    int tx = threadIdx.x, ty = threadIdx.y;
    const float* Ts = (sx < Spay) ? Tre : Tim;
    int sl = sx & (Spay - 1);
#pragma unroll
    for (int i = 0; i < 4; i++) {
        int ml = ty + i * 8;
        tile[tx][ml] = Ts[(my + ml) * Spay + sl + tx];
    }
    __syncthreads();
#pragma unroll
    for (int i = 0; i < 4; i++) {
        int srow = sx + ty + i * 8;
        float v = tile[ty + i * 8][tx];
        hsplit(&g_Tth[(size_t)srow * Mcb + my + tx], &g_Ttl[(size_t)srow * Mcb + my + tx], v);
    }
}

// ---------------------------------------------------------------------------
// wkern: tiered fp16 mma.sync 5-acc GEMM (128b x 64m), 512 threads / 16 warps.
// 12 chunks: grp0 (4) = hh all 5 dots; grp1 (4) = zl x {B0h,B1h} (a1,a2);
// grp2 (4) = zh x {B0l,B1l} (a1,a2). 9 effective K-passes vs 15.
// ---------------------------------------------------------------------------
#define WA_REG 32768
#define WB_REG 24576
#define WSTG   (WA_REG + WB_REG)   // 57344
#define WSMEM  (3 * WSTG)          // 172032

__global__ __launch_bounds__(512, 1) void wkern() {
    extern __shared__ __align__(16) uint8_t sm[];
    const uint32_t smb = smem_u32(sm);
    const int t = threadIdx.x, wid = t >> 5, lane = t & 31;
    const int mCTA = blockIdx.x, bCTA = blockIdx.y;
    const int wb = wid >> 2, wm = wid & 3;   // 4 b-groups x 4 m-groups

    float acc[5][2][2][4] = {};   // [prod][bt][nt(h)][frag]

    auto issue = [&](int ch) {
        int s = ch % 3;
        int grp = ch >> 2;
        int k0 = (ch & 3) * 64;
        uint32_t dstA = smb + s * WSTG;
        uint32_t dstB = dstA + WA_REG;
        if (grp == 0) {
            const __half* As[2] = { g_Ah[0], g_Ah[1] };
            const __half* Bs[3] = { g_Bh[0], g_Bh[1], g_Bh[2] };
#pragma unroll
            for (int i = 0; i < 4; i++) {      // A: 2048 granules
                int g = i * 512 + t;
                int var = g >> 10, row = (g >> 3) & 127, c16 = g & 7;
                cpa16(dstA + var*16384 + swz(row*128 + c16*16),
                      As[var] + (size_t)(bCTA*128 + row)*256 + k0 + c16*8);
            }
#pragma unroll
            for (int i = 0; i < 3; i++) {      // B: 1536 granules
                int g = i * 512 + t;
                int var = g >> 9, row = (g >> 3) & 63, c16 = g & 7;
                cpa16(dstB + var*8192 + swz(row*128 + c16*16),
                      Bs[var] + (size_t)(mCTA*64 + row)*256 + k0 + c16*8);
            }
        } else {
            const __half* Aone = (grp == 1) ? g_Al[0] : g_Ah[0];
            const __half* B0 = (grp == 1) ? g_Bh[0] : g_Bl[0];
            const __half* B1 = (grp == 1) ? g_Bh[1] : g_Bl[1];
#pragma unroll
            for (int i = 0; i < 2; i++) {      // A: 1024 granules (slot 0 only)
                int g = i * 512 + t;
                int row = g >> 3, c16 = g & 7;
                cpa16(dstA + swz(row*128 + c16*16),
                      Aone + (size_t)(bCTA*128 + row)*256 + k0 + c16*8);
            }
#pragma unroll
            for (int i = 0; i < 2; i++) {      // B: 1024 granules (slots 0,1)
                int g = i * 512 + t;
                int var = g >> 9, row = (g >> 3) & 63, c16 = g & 7;
                cpa16(dstB + var*8192 + swz(row*128 + c16*16),
                      (var ? B1 : B0) + (size_t)(mCTA*64 + row)*256 + k0 + c16*8);
            }
        }
        cpa_commit();
    };

    const int arow = wb*32 + ((lane >> 3) & 1)*8 + (lane & 7);
    const int ac16 = lane >> 4;
    const int brow_in = ((lane >> 4) ? 8 : 0) + (lane & 7);
    const int bk16 = (lane >> 3) & 1;

    auto compute_full = [&](int s) {
        uint32_t baseA = smb + s * WSTG;
        uint32_t baseB = baseA + WA_REG;
#pragma unroll
        for (int kt = 0; kt < 4; kt++) {
            uint32_t af[2][2][4];
#pragma unroll
            for (int var = 0; var < 2; var++)
#pragma unroll
                for (int bt = 0; bt < 2; bt++) {
                    uint32_t o = (uint32_t)(arow + bt*16)*128 + (kt*2 + ac16)*16;
                    ldmx4(af[var][bt], baseA + var*16384 + swz(o));
                }
#pragma unroll
            for (int VAR = 0; VAR < 3; VAR++) {
                uint32_t bf[4];
                uint32_t o = (uint32_t)(wm*16 + brow_in)*128 + (kt*2 + bk16)*16;
                ldmx4(bf, baseB + VAR*8192 + swz(o));
#pragma unroll
                for (int h = 0; h < 2; h++) {
                    const uint32_t* bsel = &bf[h*2];
                    if (VAR == 0) {
                        mma_f16(acc[0][0][h], af[0][0], bsel); mma_f16(acc[0][1][h], af[0][1], bsel);
                        mma_f16(acc[3][0][h], af[1][0], bsel); mma_f16(acc[3][1][h], af[1][1], bsel);
                    } else if (VAR == 1) {
                        mma_f16(acc[1][0][h], af[0][0], bsel); mma_f16(acc[1][1][h], af[0][1], bsel);
                        mma_f16(acc[4][0][h], af[1][0], bsel); mma_f16(acc[4][1][h], af[1][1], bsel);
                    } else {
                        mma_f16(acc[2][0][h], af[0][0], bsel); mma_f16(acc[2][1][h], af[0][1], bsel);
                    }
                }
            }
        }
    };

    auto compute_part = [&](int s) {
        uint32_t baseA = smb + s * WSTG;
        uint32_t baseB = baseA + WA_REG;
#pragma unroll
        for (int kt = 0; kt < 4; kt++) {
            uint32_t af[2][4];
#pragma unroll
            for (int bt = 0; bt < 2; bt++) {
                uint32_t o = (uint32_t)(arow + bt*16)*128 + (kt*2 + ac16)*16;
                ldmx4(af[bt], baseA + swz(o));
            }
#pragma unroll
            for (int VAR = 0; VAR < 2; VAR++) {
                uint32_t bf[4];
                uint32_t o = (uint32_t)(wm*16 + brow_in)*128 + (kt*2 + bk16)*16;
                ldmx4(bf, baseB + VAR*8192 + swz(o));
#pragma unroll
                for (int h = 0; h < 2; h++) {
                    const uint32_t* bsel = &bf[h*2];
                    mma_f16(acc[VAR][0][h], af[0], bsel);
                    mma_f16(acc[VAR][1][h], af[1], bsel);
                }
            }
        }
    };

    issue(0);
    issue(1);
    for (int ch = 0; ch < 12; ch++) {
        if (ch < 11) cpa_wait1(); else cpa_wait0();
        __syncthreads();
        if (ch < 10) issue(ch + 2);
        if ((ch >> 2) == 0) compute_full(ch % 3); else compute_part(ch % 3);
    }

    // ---- epilogue ----
    const int mBase = mCTA*64 + wm*16 + ((lane & 3) << 1);
    float2 crv[2], civ[2], zjv[2], ipv[2], iqv[2], wfv[2], scv[2];
#pragma unroll
    for (int nt = 0; nt < 2; nt++) {
        int m = mBase + nt*8;
        crv[nt] = *(const float2*)&g_cr[m];   civ[nt] = *(const float2*)&g_ci[m];
        zjv[nt] = *(const float2*)&g_zj2[m];  ipv[nt] = *(const float2*)&g_isp[m];
        iqv[nt] = *(const float2*)&g_isq[m];  wfv[nt] = *(const float2*)&g_wfac[m];
        scv[nt] = *(const float2*)&g_scale[m];
    }
    const int rBase = bCTA*128 + wb*32 + (lane >> 2);

#pragma unroll
    for (int bt = 0; bt < 2; bt++) {
        float rs[2] = {0.0f, 0.0f};
        float wv[2][4];
        float z2v[2] = { g_z2[rBase + bt*16], g_z2[rBase + bt*16 + 8] };
#pragma unroll
        for (int nt = 0; nt < 2; nt++) {
#pragma unroll
            for (int c = 0; c < 4; c++) {
                int h = c >> 1, j = c & 1;
                float cr = j ? crv[nt].y : crv[nt].x;
                float ci = j ? civ[nt].y : civ[nt].x;
                float zj = j ? zjv[nt].y : zjv[nt].x;
                float ip = j ? ipv[nt].y : ipv[nt].x;
                float iq = j ? iqv[nt].y : iqv[nt].x;
                float wf = j ? wfv[nt].y : wfv[nt].x;
                float sc = j ? scv[nt].y : scv[nt].x;
                float a1 = acc[0][bt][nt][c], a2 = acc[1][bt][nt][c];
                float a3 = acc[2][bt][nt][c], a4 = acc[3][bt][nt][c], a5 = acc[4][bt][nt][c];
                float pr = a1 - cr;
                float pim = a2 - ci;
                float dz2 = z2v[h] + zj - 2.0f * a3;
                float perp2 = fmaxf(dz2 - (pr*pr + pim*pim), 0.0f);
                float align_ = a4*a4 + a5*a5;
                float base = -ip * (pim*pim) - iq * perp2;
                float ssum = 0.0f;
#pragma unroll
                for (int k = 0; k < 8; k++) {
                    float d = pr - GHT[k] * sc;
                    ssum += GHW[k] * __expf(fmaf(-ip * d, d, base));
                }
                float w = wf * align_ * ssum;
                wv[nt][c] = w;
                rs[h] += w;
            }
        }
#pragma unroll
        for (int h = 0; h < 2; h++) {
            float v = rs[h];
            v += __shfl_xor_sync(0xffffffffu, v, 1);
            v += __shfl_xor_sync(0xffffffffu, v, 2);
            if ((lane & 3) == 0)
                g_dpart[(rBase + bt*16 + h*8) * 512 + mCTA*4 + wm] = v;
        }
#pragma unroll
        for (int h = 0; h < 2; h++) {
            size_t rowoff = (size_t)(rBase + bt*16 + h*8) * Mcb;
#pragma unroll
            for (int nt = 0; nt < 2; nt++) {
                uint32_t hw, lw;
                split2h(wv[nt][h*2], wv[nt][h*2 + 1], hw, lw);
                *(uint32_t*)&g_Whi[rowoff + mBase + nt*8] = hw;
                *(uint32_t*)&g_Wlo[rowoff + mBase + nt*8] = lw;
            }
        }
    }
}

// ---------------------------------------------------------------------------
__global__ void denk() {
    int b = blockIdx.x, t = threadIdx.x;
    __shared__ float sh[256];
    sh[t] = g_dpart[b * 512 + t] + g_dpart[b * 512 + 256 + t];
    __syncthreads();
    for (int o = 128; o > 0; o >>= 1) { if (t < o) sh[t] += sh[t + o]; __syncthreads(); }
    if (t == 0) g_den[b] = sh[0] + EPST;
}

// ---------------------------------------------------------------------------
// outk: partial out = W @ Tcat over a K-split. CTA 64b x 64scat, fp16 3-product.
// ---------------------------------------------------------------------------
#define OTILE 8192
#define OSTG  (4 * OTILE)   // 32768
#define OSMEM (3 * OSTG)    // 98304

__global__ __launch_bounds__(256, 2) void outk() {
    extern __shared__ __align__(16) uint8_t sm[];
    const uint32_t smb = smem_u32(sm);
    const int t = threadIdx.x, wid = t >> 5, lane = t & 31;
    const int sCTA = blockIdx.x, bCTA = blockIdx.y, kz = blockIdx.z;
    const int wb = wid >> 1, ws = wid & 1;
    const int b0 = bCTA * 64, s0 = sCTA * 64;
    const int kbase = kz * 4096;

    float acc[4][4] = {};

    auto issue = [&](int ch) {
        int s = ch % 3;
        int k0 = kbase + ch * 64;
        uint32_t dst = smb + s * OSTG;
        const __half* srcs[4] = { g_Whi, g_Wlo, g_Tth, g_Ttl };
        const int r0[4] = { b0, b0, s0, s0 };
#pragma unroll
        for (int ti = 0; ti < 4; ti++) {
#pragma unroll
            for (int i = 0; i < 2; i++) {
                int g = i * 256 + t;
                int row = g >> 3, c16 = g & 7;
                cpa16(dst + ti*OTILE + swz(row*128 + c16*16),
                      srcs[ti] + (size_t)(r0[ti] + row)*Mcb + k0 + c16*8);
            }
        }
        cpa_commit();
    };

    const int arow = wb*16 + ((lane >> 3) & 1)*8 + (lane & 7);
    const int ac16 = lane >> 4;
    const int brow_in = ((lane >> 4) ? 8 : 0) + (lane & 7);
    const int bk16 = (lane >> 3) & 1;

    auto compute = [&](int s) {
        uint32_t base = smb + s * OSTG;
#pragma unroll
        for (int kt = 0; kt < 4; kt++) {
            uint32_t ah[4], al[4];
            uint32_t oA = (uint32_t)arow*128 + (kt*2 + ac16)*16;
            ldmx4(ah, base + swz(oA));
            ldmx4(al, base + OTILE + swz(oA));
#pragma unroll
            for (int np = 0; np < 2; np++) {
                uint32_t bh[4], bl[4];
                uint32_t oB = (uint32_t)((ws*4 + np*2)*8 + brow_in)*128 + (kt*2 + bk16)*16;
                ldmx4(bh, base + 2*OTILE + swz(oB));
                ldmx4(bl, base + 3*OTILE + swz(oB));
#pragma unroll
                for (int h = 0; h < 2; h++) {
                    float* a = acc[np*2 + h];
                    mma_f16(a, ah, &bh[h*2]);
                    mma_f16(a, al, &bh[h*2]);
                    mma_f16(a, ah, &bl[h*2]);
                }
            }
        }
    };

    issue(0);
    issue(1);
    for (int ch = 0; ch < 64; ch++) {
        if (ch < 63) cpa_wait1(); else cpa_wait0();
        __syncthreads();
        if (ch < 62) issue(ch + 2);
        compute(ch % 3);
    }

    const int sBase = s0 + ws*32 + ((lane & 3) << 1);
    const int rB = b0 + wb*16 + (lane >> 2);
    float* part = g_opart + (size_t)kz * Bq * 512;
#pragma unroll
    for (int h = 0; h < 2; h++) {
        int b = rB + h*8;
#pragma unroll
        for (int nt = 0; nt < 4; nt++) {
            int scat = sBase + nt*8;
            *(float2*)&part[(size_t)b * 512 + scat] =
                make_float2(acc[nt][h*2], acc[nt][h*2 + 1]);
        }
    }
}

// ---------------------------------------------------------------------------
__global__ void fink(float* __restrict__ out) {
    int b = blockIdx.x, t = threadIdx.x;
    float inv = 1.0f / g_den[b];
#pragma unroll
    for (int i = 0; i < 2; i++) {
        int scat = i * 256 + t;
        float v = (g_opart[(size_t)b * 512 + scat] +
                   g_opart[(size_t)(Bq + b) * 512 + scat]) * inv;
        int c = scat >> 8;
        int sl = scat & (Spay - 1);
        out[((size_t)b * Spay + sl) * 2 + c] = v;
    }
}

// ---------------------------------------------------------------------------
extern "C" void kernel_launch(void* const* d_in, const int* in_sizes, int n_in,
                              void* d_out, int out_size) {
    const float* z_re  = (const float*)d_in[0];
    const float* z_im  = (const float*)d_in[1];
    const float* d_re  = (const float*)d_in[2];
    const float* d_im  = (const float*)d_in[3];
    const float* zj_re = (const float*)d_in[4];
    const float* zj_im = (const float*)d_in[5];
    const float* dj_re = (const float*)d_in[6];
    const float* dj_im = (const float*)d_in[7];
    const float* T_re  = (const float*)d_in[8];
    const float* T_im  = (const float*)d_in[9];
    const float* alpha = (const float*)d_in[10];
    const float* s_par = (const float*)d_in[11];
    const float* s_perp = (const float*)d_in[12];
    float* out = (float*)d_out;

    cudaFuncSetAttribute(wkern, cudaFuncAttributeMaxDynamicSharedMemorySize, WSMEM);
    cudaFuncSetAttribute(outk,  cudaFuncAttributeMaxDynamicSharedMemorySize, OSMEM);

    prep_q<<<Bq, 128>>>(z_re, z_im, d_re, d_im);
    prep_c<<<Mcb, 128>>>(zj_re, zj_im, dj_re, dj_im, alpha, s_par, s_perp);
    prep_T<<<dim3(512 / 32, Mcb / 32), dim3(32, 8)>>>(T_re, T_im);
    wkern<<<dim3(Mcb / 64, Bq / 128), 512, WSMEM>>>();
    denk<<<Bq, 256>>>();
    outk<<<dim3(8, 16, 2), 256, OSMEM>>>();
    fink<<<Bq, 256>>>(out);
}

// round 10
// speedup vs baseline: 2.5868x; 1.0967x over previous
#include <cuda_runtime.h>
#include <cuda_fp16.h>
#include <math.h>
#include <stdint.h>

#define Bq   1024
#define Ndim 128
#define Mcb  8192
#define Spay 256
#define EPST 1e-3f
#define PI_F 3.14159265358979323846f
#define TINY 1.17549435e-38f

__constant__ float GHT[8] = {
    -2.9306374202572440f, -1.9816567566958429f, -1.1571937124467802f, -0.3811869902073221f,
     0.3811869902073221f,  1.1571937124467802f,  1.9816567566958429f,  2.9306374202572440f};
__constant__ float GHW[8] = {
    1.9960407221136762e-04f, 1.7077983007413475e-02f, 2.0780232581489188e-01f, 6.6114701255824130e-01f,
    6.6114701255824130e-01f, 2.0780232581489188e-01f, 1.7077983007413475e-02f, 1.9960407221136762e-04f};

// ---------------- scratch (fp16 hi/lo splits, row-major) ----------------
__device__ __align__(16) __half g_Ah[2][Bq * 256];   // A var 0=[zr|zi], 1=[ur|ui]
__device__ __align__(16) __half g_Al[2][Bq * 256];
__device__ __align__(16) __half g_Bh[3][Mcb * 256];  // B var 0=[ar|ai], 1=[-ai|ar], 2=[br|bi]
__device__ __align__(16) __half g_Bl[3][Mcb * 256];
__device__ __align__(16) __half g_Tth[512 * Mcb];    // Tcat^T [scat][m] (fp16-rounded)
__device__ __align__(16) __half g_Whi[(size_t)Bq * Mcb];  // W [b][m]
__device__ __align__(16) __half g_Wlo[(size_t)Bq * Mcb];
__device__ __align__(16) float g_cr[Mcb], g_ci[Mcb], g_zj2[Mcb];
__device__ __align__(16) float g_isp[Mcb], g_isq[Mcb], g_wfac[Mcb], g_scale[Mcb];
__device__ float g_z2[Bq];
__device__ float g_den[Bq];
__device__ float g_dpart[Bq * 512];
__device__ float g_opart[2 * Bq * 512];

// ---------------- helpers ----------------
__device__ __forceinline__ uint32_t smem_u32(const void* p) {
    uint32_t a;
    asm("{ .reg .u64 t; cvta.to.shared.u64 t, %1; cvt.u32.u64 %0, t; }" : "=r"(a) : "l"(p));
    return a;
}
__device__ __forceinline__ void cpa16(uint32_t s, const void* g) {
    asm volatile("{ .reg .u64 gg; cvta.to.global.u64 gg, %1; cp.async.cg.shared.global [%0], [gg], 16; }"
                 :: "r"(s), "l"(g) : "memory");
}
__device__ __forceinline__ void cpa_commit() { asm volatile("cp.async.commit_group;" ::: "memory"); }
__device__ __forceinline__ void cpa_wait0() { asm volatile("cp.async.wait_group 0;" ::: "memory"); }
__device__ __forceinline__ void cpa_wait1() { asm volatile("cp.async.wait_group 1;" ::: "memory"); }

__device__ __forceinline__ void mma_f16(float* d, const uint32_t* a, const uint32_t* b) {
    asm volatile("mma.sync.aligned.m16n8k16.row.col.f32.f16.f16.f32 "
                 "{%0,%1,%2,%3}, {%4,%5,%6,%7}, {%8,%9}, {%0,%1,%2,%3};"
                 : "+f"(d[0]), "+f"(d[1]), "+f"(d[2]), "+f"(d[3])
                 : "r"(a[0]), "r"(a[1]), "r"(a[2]), "r"(a[3]), "r"(b[0]), "r"(b[1]));
}
__device__ __forceinline__ void ldmx4(uint32_t* r, uint32_t a) {
    asm volatile("ldmatrix.sync.aligned.m8n8.x4.shared.b16 {%0,%1,%2,%3}, [%4];"
                 : "=r"(r[0]), "=r"(r[1]), "=r"(r[2]), "=r"(r[3]) : "r"(a));
}
__device__ __forceinline__ uint32_t swz(uint32_t o) { return o ^ ((o >> 3) & 0x70); }

__device__ __forceinline__ void hsplit(__half* ph, __half* pl, float x) {
    __half h = __float2half_rn(x);
    *ph = h;
    *pl = __float2half_rn(x - __half2float(h));
}
__device__ __forceinline__ void split2h(float x, float y, uint32_t& hw, uint32_t& lw) {
    __half hx = __float2half_rn(x), hy = __float2half_rn(y);
    __half lx = __float2half_rn(x - __half2float(hx));
    __half ly = __float2half_rn(y - __half2float(hy));
    hw = ((uint32_t)__half_as_ushort(hy) << 16) | __half_as_ushort(hx);
    lw = ((uint32_t)__half_as_ushort(ly) << 16) | __half_as_ushort(lx);
}

// ---------------------------------------------------------------------------
// prep kernels
// ---------------------------------------------------------------------------
__global__ void prep_q(const float* __restrict__ zr, const float* __restrict__ zi,
                       const float* __restrict__ dr, const float* __restrict__ di) {
    int b = blockIdx.x, t = threadIdx.x;
    __shared__ float s1[128], s2[128];
    float drv = dr[b*Ndim+t], dvv = di[b*Ndim+t];
    float zrv = zr[b*Ndim+t], ziv = zi[b*Ndim+t];
    s1[t] = drv*drv + dvv*dvv;
    s2[t] = zrv*zrv + ziv*ziv;
    __syncthreads();
    for (int o = 64; o > 0; o >>= 1) { if (t < o) { s1[t]+=s1[t+o]; s2[t]+=s2[t+o]; } __syncthreads(); }
    float n = sqrtf(s1[0]); if (n == 0.0f) n = 1.0f;
    float inv = 1.0f / n;
    float ur = drv*inv, ui = dvv*inv;
    hsplit(&g_Ah[0][b*256+t],     &g_Al[0][b*256+t],     zrv);
    hsplit(&g_Ah[0][b*256+128+t], &g_Al[0][b*256+128+t], ziv);
    hsplit(&g_Ah[1][b*256+t],     &g_Al[1][b*256+t],     ur);
    hsplit(&g_Ah[1][b*256+128+t], &g_Al[1][b*256+128+t], ui);
    if (t == 0) g_z2[b] = s2[0];
}

__global__ void prep_c(const float* __restrict__ zjr, const float* __restrict__ zji,
                       const float* __restrict__ djr, const float* __restrict__ dji,
                       const float* __restrict__ alpha, const float* __restrict__ spv,
                       const float* __restrict__ sqv) {
    int m = blockIdx.x, t = threadIdx.x;
    __shared__ float s1[128], s2[128], s3[128];
    float ar = djr[m*Ndim+t], ai = dji[m*Ndim+t];
    s1[t] = ar*ar + ai*ai;
    __syncthreads();
    for (int o = 64; o > 0; o >>= 1) { if (t < o) s1[t]+=s1[t+o]; __syncthreads(); }
    float n = sqrtf(s1[0]); if (n == 0.0f) n = 1.0f;
    float inv = 1.0f / n;
    ar *= inv; ai *= inv;
    float br = zjr[m*Ndim+t], bi = zji[m*Ndim+t];
    hsplit(&g_Bh[0][m*256+t],     &g_Bl[0][m*256+t],     ar);
    hsplit(&g_Bh[0][m*256+128+t], &g_Bl[0][m*256+128+t], ai);
    hsplit(&g_Bh[1][m*256+t],     &g_Bl[1][m*256+t],     -ai);
    hsplit(&g_Bh[1][m*256+128+t], &g_Bl[1][m*256+128+t], ar);
    hsplit(&g_Bh[2][m*256+t],     &g_Bl[2][m*256+t],     br);
    hsplit(&g_Bh[2][m*256+128+t], &g_Bl[2][m*256+128+t], bi);
    __syncthreads();
    s1[t] = ar*br + ai*bi;
    s2[t] = ar*bi - ai*br;
    s3[t] = br*br + bi*bi;
    __syncthreads();
    for (int o = 64; o > 0; o >>= 1) {
        if (t < o) { s1[t]+=s1[t+o]; s2[t]+=s2[t+o]; s3[t]+=s3[t+o]; }
        __syncthreads();
    }
    if (t == 0) {
        float a  = fmaxf(alpha[m], TINY);
        float sp = fmaxf(spv[m], TINY);
        float sq = fmaxf(sqv[m], TINY);
        g_cr[m] = s1[0]; g_ci[m] = s2[0]; g_zj2[m] = s3[0];
        g_isp[m] = PI_F / sp;
        g_isq[m] = PI_F / sq;
        g_scale[m] = sqrtf(sp / PI_F);
        g_wfac[m] = a * sqrtf(sp) / PI_F;
    }
}

// Tcat^T[scat][m], fp16-rounded (hi only).  grid (16, 256), block (32, 8)
__global__ void prep_T(const float* __restrict__ Tre, const float* __restrict__ Tim) {
    __shared__ float tile[32][33];
    int sx = blockIdx.x * 32, my = blockIdx.y * 32;
    int tx = threadIdx.x, ty = threadIdx.y;
    const float* Ts = (sx < Spay) ? Tre : Tim;
    int sl = sx & (Spay - 1);
#pragma unroll
    for (int i = 0; i < 4; i++) {
        int ml = ty + i * 8;
        tile[tx][ml] = Ts[(my + ml) * Spay + sl + tx];
    }
    __syncthreads();
#pragma unroll
    for (int i = 0; i < 4; i++) {
        int srow = sx + ty + i * 8;
        float v = tile[ty + i * 8][tx];
        g_Tth[(size_t)srow * Mcb + my + tx] = __float2half_rn(v);
    }
}

// ---------------------------------------------------------------------------
// wkern: tiered fp16 mma.sync 5-acc GEMM (128b x 64m), 512 threads / 16 warps.
// 12 chunks: grp0 (4) = hh all 5 dots; grp1 (4) = u_lo x {B0h,B1h} (a4,a5);
// grp2 (4) = u_hi x {B0l,B1l} (a4,a5). Crosses spent on align (error-dominant).
// ---------------------------------------------------------------------------
#define WA_REG 32768
#define WB_REG 24576
#define WSTG   (WA_REG + WB_REG)   // 57344
#define WSMEM  (3 * WSTG)          // 172032

__global__ __launch_bounds__(512, 1) void wkern() {
    extern __shared__ __align__(16) uint8_t sm[];
    const uint32_t smb = smem_u32(sm);
    const int t = threadIdx.x, wid = t >> 5, lane = t & 31;
    const int mCTA = blockIdx.x, bCTA = blockIdx.y;
    const int wb = wid >> 2, wm = wid & 3;   // 4 b-groups x 4 m-groups

    float acc[5][2][2][4] = {};   // [prod][bt][nt(h)][frag]

    auto issue = [&](int ch) {
        int s = ch % 3;
        int grp = ch >> 2;
        int k0 = (ch & 3) * 64;
        uint32_t dstA = smb + s * WSTG;
        uint32_t dstB = dstA + WA_REG;
        if (grp == 0) {
            const __half* As[2] = { g_Ah[0], g_Ah[1] };
            const __half* Bs[3] = { g_Bh[0], g_Bh[1], g_Bh[2] };
#pragma unroll
            for (int i = 0; i < 4; i++) {      // A: 2048 granules
                int g = i * 512 + t;
                int var = g >> 10, row = (g >> 3) & 127, c16 = g & 7;
                cpa16(dstA + var*16384 + swz(row*128 + c16*16),
                      As[var] + (size_t)(bCTA*128 + row)*256 + k0 + c16*8);
            }
#pragma unroll
            for (int i = 0; i < 3; i++) {      // B: 1536 granules
                int g = i * 512 + t;
                int var = g >> 9, row = (g >> 3) & 63, c16 = g & 7;
                cpa16(dstB + var*8192 + swz(row*128 + c16*16),
                      Bs[var] + (size_t)(mCTA*64 + row)*256 + k0 + c16*8);
            }
        } else {
            // crosses for a4/a5: u_lo x B_hi (grp1), u_hi x B_lo (grp2)
            const __half* Aone = (grp == 1) ? g_Al[1] : g_Ah[1];
            const __half* B0 = (grp == 1) ? g_Bh[0] : g_Bl[0];
            const __half* B1 = (grp == 1) ? g_Bh[1] : g_Bl[1];
#pragma unroll
            for (int i = 0; i < 2; i++) {      // A: 1024 granules (slot 0 only)
                int g = i * 512 + t;
                int row = g >> 3, c16 = g & 7;
                cpa16(dstA + swz(row*128 + c16*16),
                      Aone + (size_t)(bCTA*128 + row)*256 + k0 + c16*8);
            }
#pragma unroll
            for (int i = 0; i < 2; i++) {      // B: 1024 granules (slots 0,1)
                int g = i * 512 + t;
                int var = g >> 9, row = (g >> 3) & 63, c16 = g & 7;
                cpa16(dstB + var*8192 + swz(row*128 + c16*16),
                      (var ? B1 : B0) + (size_t)(mCTA*64 + row)*256 + k0 + c16*8);
            }
        }
        cpa_commit();
    };

    const int arow = wb*32 + ((lane >> 3) & 1)*8 + (lane & 7);
    const int ac16 = lane >> 4;
    const int brow_in = ((lane >> 4) ? 8 : 0) + (lane & 7);
    const int bk16 = (lane >> 3) & 1;

    auto compute_full = [&](int s) {
        uint32_t baseA = smb + s * WSTG;
        uint32_t baseB = baseA + WA_REG;
#pragma unroll
        for (int kt = 0; kt < 4; kt++) {
            uint32_t af[2][2][4];
#pragma unroll
            for (int var = 0; var < 2; var++)
#pragma unroll
                for (int bt = 0; bt < 2; bt++) {
                    uint32_t o = (uint32_t)(arow + bt*16)*128 + (kt*2 + ac16)*16;
                    ldmx4(af[var][bt], baseA + var*16384 + swz(o));
                }
#pragma unroll
            for (int VAR = 0; VAR < 3; VAR++) {
                uint32_t bf[4];
                uint32_t o = (uint32_t)(wm*16 + brow_in)*128 + (kt*2 + bk16)*16;
                ldmx4(bf, baseB + VAR*8192 + swz(o));
#pragma unroll
                for (int h = 0; h < 2; h++) {
                    const uint32_t* bsel = &bf[h*2];
                    if (VAR == 0) {
                        mma_f16(acc[0][0][h], af[0][0], bsel); mma_f16(acc[0][1][h], af[0][1], bsel);
                        mma_f16(acc[3][0][h], af[1][0], bsel); mma_f16(acc[3][1][h], af[1][1], bsel);
                    } else if (VAR == 1) {
                        mma_f16(acc[1][0][h], af[0][0], bsel); mma_f16(acc[1][1][h], af[0][1], bsel);
                        mma_f16(acc[4][0][h], af[1][0], bsel); mma_f16(acc[4][1][h], af[1][1], bsel);
                    } else {
                        mma_f16(acc[2][0][h], af[0][0], bsel); mma_f16(acc[2][1][h], af[0][1], bsel);
                    }
                }
            }
        }
    };

    auto compute_part = [&](int s) {
        uint32_t baseA = smb + s * WSTG;
        uint32_t baseB = baseA + WA_REG;
#pragma unroll
        for (int kt = 0; kt < 4; kt++) {
            uint32_t af[2][4];
#pragma unroll
            for (int bt = 0; bt < 2; bt++) {
                uint32_t o = (uint32_t)(arow + bt*16)*128 + (kt*2 + ac16)*16;
                ldmx4(af[bt], baseA + swz(o));
            }
#pragma unroll
            for (int VAR = 0; VAR < 2; VAR++) {
                uint32_t bf[4];
                uint32_t o = (uint32_t)(wm*16 + brow_in)*128 + (kt*2 + bk16)*16;
                ldmx4(bf, baseB + VAR*8192 + swz(o));
#pragma unroll
                for (int h = 0; h < 2; h++) {
                    const uint32_t* bsel = &bf[h*2];
                    mma_f16(acc[3 + VAR][0][h], af[0], bsel);
                    mma_f16(acc[3 + VAR][1][h], af[1], bsel);
                }
            }
        }
    };

    issue(0);
    issue(1);
    for (int ch = 0; ch < 12; ch++) {
        if (ch < 11) cpa_wait1(); else cpa_wait0();
        __syncthreads();
        if (ch < 10) issue(ch + 2);
        if ((ch >> 2) == 0) compute_full(ch % 3); else compute_part(ch % 3);
    }

    // ---- epilogue ----
    const int mBase = mCTA*64 + wm*16 + ((lane & 3) << 1);
    float2 crv[2], civ[2], zjv[2], ipv[2], iqv[2], wfv[2], scv[2];
#pragma unroll
    for (int nt = 0; nt < 2; nt++) {
        int m = mBase + nt*8;
        crv[nt] = *(const float2*)&g_cr[m];   civ[nt] = *(const float2*)&g_ci[m];
        zjv[nt] = *(const float2*)&g_zj2[m];  ipv[nt] = *(const float2*)&g_isp[m];
        iqv[nt] = *(const float2*)&g_isq[m];  wfv[nt] = *(const float2*)&g_wfac[m];
        scv[nt] = *(const float2*)&g_scale[m];
    }
    const int rBase = bCTA*128 + wb*32 + (lane >> 2);

#pragma unroll
    for (int bt = 0; bt < 2; bt++) {
        float rs[2] = {0.0f, 0.0f};
        float wv[2][4];
        float z2v[2] = { g_z2[rBase + bt*16], g_z2[rBase + bt*16 + 8] };
#pragma unroll
        for (int nt = 0; nt < 2; nt++) {
#pragma unroll
            for (int c = 0; c < 4; c++) {
                int h = c >> 1, j = c & 1;
                float cr = j ? crv[nt].y : crv[nt].x;
                float ci = j ? civ[nt].y : civ[nt].x;
                float zj = j ? zjv[nt].y : zjv[nt].x;
                float ip = j ? ipv[nt].y : ipv[nt].x;
                float iq = j ? iqv[nt].y : iqv[nt].x;
                float wf = j ? wfv[nt].y : wfv[nt].x;
                float sc = j ? scv[nt].y : scv[nt].x;
                float a1 = acc[0][bt][nt][c], a2 = acc[1][bt][nt][c];
                float a3 = acc[2][bt][nt][c], a4 = acc[3][bt][nt][c], a5 = acc[4][bt][nt][c];
                float pr = a1 - cr;
                float pim = a2 - ci;
                float dz2 = z2v[h] + zj - 2.0f * a3;
                float perp2 = fmaxf(dz2 - (pr*pr + pim*pim), 0.0f);
                float align_ = a4*a4 + a5*a5;
                float base = -ip * (pim*pim) - iq * perp2;
                float ssum = 0.0f;
#pragma unroll
                for (int k = 0; k < 8; k++) {
                    float d = pr - GHT[k] * sc;
                    ssum += GHW[k] * __expf(fmaf(-ip * d, d, base));
                }
                float w = wf * align_ * ssum;
                wv[nt][c] = w;
                rs[h] += w;
            }
        }
#pragma unroll
        for (int h = 0; h < 2; h++) {
            float v = rs[h];
            v += __shfl_xor_sync(0xffffffffu, v, 1);
            v += __shfl_xor_sync(0xffffffffu, v, 2);
            if ((lane & 3) == 0)
                g_dpart[(rBase + bt*16 + h*8) * 512 + mCTA*4 + wm] = v;
        }
#pragma unroll
        for (int h = 0; h < 2; h++) {
            size_t rowoff = (size_t)(rBase + bt*16 + h*8) * Mcb;
#pragma unroll
            for (int nt = 0; nt < 2; nt++) {
                uint32_t hw, lw;
                split2h(wv[nt][h*2], wv[nt][h*2 + 1], hw, lw);
                *(uint32_t*)&g_Whi[rowoff + mBase + nt*8] = hw;
                *(uint32_t*)&g_Wlo[rowoff + mBase + nt*8] = lw;
            }
        }
    }
}

// ---------------------------------------------------------------------------
__global__ void denk() {
    int b = blockIdx.x, t = threadIdx.x;
    __shared__ float sh[256];
    sh[t] = g_dpart[b * 512 + t] + g_dpart[b * 512 + 256 + t];
    __syncthreads();
    for (int o = 128; o > 0; o >>= 1) { if (t < o) sh[t] += sh[t + o]; __syncthreads(); }
    if (t == 0) g_den[b] = sh[0] + EPST;
}

// ---------------------------------------------------------------------------
// outk: partial out = W @ Tcat over a K-split. CTA 64b x 64scat.
// 2 products: (Whi + Wlo) x Th. 3 tiles/chunk.
// ---------------------------------------------------------------------------
#define OTILE 8192
#define OSTG  (3 * OTILE)   // 24576
#define OSMEM (3 * OSTG)    // 73728

__global__ __launch_bounds__(256, 2) void outk() {
    extern __shared__ __align__(16) uint8_t sm[];
    const uint32_t smb = smem_u32(sm);
    const int t = threadIdx.x, wid = t >> 5, lane = t & 31;
    const int sCTA = blockIdx.x, bCTA = blockIdx.y, kz = blockIdx.z;
    const int wb = wid >> 1, ws = wid & 1;
    const int b0 = bCTA * 64, s0 = sCTA * 64;
    const int kbase = kz * 4096;

    float acc[4][4] = {};

    auto issue = [&](int ch) {
        int s = ch % 3;
        int k0 = kbase + ch * 64;
        uint32_t dst = smb + s * OSTG;
        const __half* srcs[3] = { g_Whi, g_Wlo, g_Tth };
        const int r0[3] = { b0, b0, s0 };
#pragma unroll
        for (int ti = 0; ti < 3; ti++) {
#pragma unroll
            for (int i = 0; i < 2; i++) {
                int g = i * 256 + t;
                int row = g >> 3, c16 = g & 7;
                cpa16(dst + ti*OTILE + swz(row*128 + c16*16),
                      srcs[ti] + (size_t)(r0[ti] + row)*Mcb + k0 + c16*8);
            }
        }
        cpa_commit();
    };

    const int arow = wb*16 + ((lane >> 3) & 1)*8 + (lane & 7);
    const int ac16 = lane >> 4;
    const int brow_in = ((lane >> 4) ? 8 : 0) + (lane & 7);
    const int bk16 = (lane >> 3) & 1;

    auto compute = [&](int s) {
        uint32_t base = smb + s * OSTG;
#pragma unroll
        for (int kt = 0; kt < 4; kt++) {
            uint32_t ah[4], al[4];
            uint32_t oA = (uint32_t)arow*128 + (kt*2 + ac16)*16;
            ldmx4(ah, base + swz(oA));
            ldmx4(al, base + OTILE + swz(oA));
#pragma unroll
            for (int np = 0; np < 2; np++) {
                uint32_t bh[4];
                uint32_t oB = (uint32_t)((ws*4 + np*2)*8 + brow_in)*128 + (kt*2 + bk16)*16;
                ldmx4(bh, base + 2*OTILE + swz(oB));
#pragma unroll
                for (int h = 0; h < 2; h++) {
                    float* a = acc[np*2 + h];
                    mma_f16(a, ah, &bh[h*2]);
                    mma_f16(a, al, &bh[h*2]);
                }
            }
        }
    };

    issue(0);
    issue(1);
    for (int ch = 0; ch < 64; ch++) {
        if (ch < 63) cpa_wait1(); else cpa_wait0();
        __syncthreads();
        if (ch < 62) issue(ch + 2);
        compute(ch % 3);
    }

    const int sBase = s0 + ws*32 + ((lane & 3) << 1);
    const int rB = b0 + wb*16 + (lane >> 2);
    float* part = g_opart + (size_t)kz * Bq * 512;
#pragma unroll
    for (int h = 0; h < 2; h++) {
        int b = rB + h*8;
#pragma unroll
        for (int nt = 0; nt < 4; nt++) {
            int scat = sBase + nt*8;
            *(float2*)&part[(size_t)b * 512 + scat] =
                make_float2(acc[nt][h*2], acc[nt][h*2 + 1]);
        }
    }
}

// ---------------------------------------------------------------------------
__global__ void fink(float* __restrict__ out) {
    int b = blockIdx.x, t = threadIdx.x;
    float inv = 1.0f / g_den[b];
#pragma unroll
    for (int i = 0; i < 2; i++) {
        int scat = i * 256 + t;
        float v = (g_opart[(size_t)b * 512 + scat] +
                   g_opart[(size_t)(Bq + b) * 512 + scat]) * inv;
        int c = scat >> 8;
        int sl = scat & (Spay - 1);
        out[((size_t)b * Spay + sl) * 2 + c] = v;
    }
}

// ---------------------------------------------------------------------------
extern "C" void kernel_launch(void* const* d_in, const int* in_sizes, int n_in,
                              void* d_out, int out_size) {
    const float* z_re  = (const float*)d_in[0];
    const float* z_im  = (const float*)d_in[1];
    const float* d_re  = (const float*)d_in[2];
    const float* d_im  = (const float*)d_in[3];
    const float* zj_re = (const float*)d_in[4];
    const float* zj_im = (const float*)d_in[5];
    const float* dj_re = (const float*)d_in[6];
    const float* dj_im = (const float*)d_in[7];
    const float* T_re  = (const float*)d_in[8];
    const float* T_im  = (const float*)d_in[9];
    const float* alpha = (const float*)d_in[10];
    const float* s_par = (const float*)d_in[11];
    const float* s_perp = (const float*)d_in[12];
    float* out = (float*)d_out;

    cudaFuncSetAttribute(wkern, cudaFuncAttributeMaxDynamicSharedMemorySize, WSMEM);
    cudaFuncSetAttribute(outk,  cudaFuncAttributeMaxDynamicSharedMemorySize, OSMEM);

    prep_q<<<Bq, 128>>>(z_re, z_im, d_re, d_im);
    prep_c<<<Mcb, 128>>>(zj_re, zj_im, dj_re, dj_im, alpha, s_par, s_perp);
    prep_T<<<dim3(512 / 32, Mcb / 32), dim3(32, 8)>>>(T_re, T_im);
    wkern<<<dim3(Mcb / 64, Bq / 128), 512, WSMEM>>>();
    denk<<<Bq, 256>>>();
    outk<<<dim3(8, 16, 2), 256, OSMEM>>>();
    fink<<<Bq, 256>>>(out);
}